// round 1
// baseline (speedup 1.0000x reference)
#include <cuda_runtime.h>
#include <cuda_bf16.h>

// Problem dims
#define NB   8
#define SQ   1024
#define EE   1024
#define HH   16
#define DK   64

// -------------------- scratch (static device arrays; no allocation) -----------
__device__ float g_q[NB * HH * SQ * DK];     // [n,h,s,d]
__device__ float g_k[NB * HH * SQ * DK];
__device__ float g_v[NB * HH * SQ * DK];
__device__ float g_ao[NB * SQ * EE];         // attention output, [n,s,e]
__device__ unsigned char g_mask8[NB * SQ * SQ];
__device__ int g_mask_fmt;                   // 0=i32, 1=f32, 2=u8

// -------------------- mask dtype detection + conversion ----------------------
__global__ void detect_mask_kernel(const unsigned int* __restrict__ m) {
    __shared__ int s01, sf;
    if (threadIdx.x == 0) { s01 = 1; sf = 1; }
    __syncthreads();
    unsigned int v = m[threadIdx.x];   // 256 words is plenty to disambiguate
    if (v > 1u) s01 = 0;
    if (v != 0u && v != 0x3F800000u) sf = 0;
    __syncthreads();
    if (threadIdx.x == 0) g_mask_fmt = s01 ? 0 : (sf ? 1 : 2);
}

__global__ void convert_mask_kernel(const void* __restrict__ m, int n) {
    int i = blockIdx.x * blockDim.x + threadIdx.x;
    if (i >= n) return;
    int fmt = g_mask_fmt;
    unsigned char v;
    if (fmt == 0)      v = (((const int*)m)[i]   != 0)    ? 1 : 0;
    else if (fmt == 1) v = (((const float*)m)[i] != 0.0f) ? 1 : 0;
    else               v = (((const unsigned char*)m)[i] != 0) ? 1 : 0;
    g_mask8[i] = v;
}

// -------------------- GEMM: out = A(8192x1024) @ W(1024x1024) + bias ----------
// 128x128 tile, BK=16, 256 threads, 8x8 per thread.
// As stored transposed [k][row] with XOR-swizzled row-blocks (conflict-light).
// headmajor: scatter output to [n,h,s,d] layout for attention.
__global__ void __launch_bounds__(256) gemm_bias_kernel(
    const float* __restrict__ A,
    const float* __restrict__ W0, const float* __restrict__ W1, const float* __restrict__ W2,
    const float* __restrict__ b0, const float* __restrict__ b1, const float* __restrict__ b2,
    float* __restrict__ o0, float* __restrict__ o1, float* __restrict__ o2,
    int headmajor)
{
    const int Kdim = EE, Ndim = EE;
    const float* W; const float* bias; float* out;
    if (blockIdx.z == 0)      { W = W0; bias = b0; out = o0; }
    else if (blockIdx.z == 1) { W = W1; bias = b1; out = o1; }
    else                      { W = W2; bias = b2; out = o2; }

    __shared__ float As[16][128];      // [k][swizzled row]
    __shared__ float Bs[16][132];      // padded

    const int tid = threadIdx.x;
    const int tx = tid & 15, ty = tid >> 4;
    const int rowBase = blockIdx.y * 128;
    const int colBase = blockIdx.x * 128;

    float acc[8][8];
#pragma unroll
    for (int i = 0; i < 8; i++)
#pragma unroll
        for (int j = 0; j < 8; j++) acc[i][j] = 0.0f;

    for (int kt = 0; kt < Kdim; kt += 16) {
        // load A tile 128x16 (512 float4s, 2 per thread), store transposed+swizzled
#pragma unroll
        for (int p = 0; p < 2; p++) {
            int f = tid + p * 256;
            int r = f >> 2;            // 0..127
            int k4 = f & 3;            // 0..3
            float4 av = *(const float4*)(A + (size_t)(rowBase + r) * Kdim + kt + k4 * 4);
            float vals[4] = {av.x, av.y, av.z, av.w};
            int rb = r >> 2, rl = r & 3;
#pragma unroll
            for (int c = 0; c < 4; c++) {
                int k = k4 * 4 + c;
                As[k][((rb ^ (k & 31)) << 2) + rl] = vals[c];
            }
        }
        // load B tile 16x128 (512 float4s, 2 per thread), natural
#pragma unroll
        for (int p = 0; p < 2; p++) {
            int f = tid + p * 256;
            int r = f >> 5;            // 0..15
            int n4 = f & 31;           // 0..31
            float4 bv = *(const float4*)(W + (size_t)(kt + r) * Ndim + colBase + n4 * 4);
            *(float4*)&Bs[r][n4 * 4] = bv;
        }
        __syncthreads();

#pragma unroll 8
        for (int k = 0; k < 16; k++) {
            int sw = k & 31;
            float a[8], b[8];
            *(float4*)&a[0] = *(const float4*)&As[k][((ty       ^ sw) << 2)];
            *(float4*)&a[4] = *(const float4*)&As[k][(((ty + 16) ^ sw) << 2)];
            *(float4*)&b[0] = *(const float4*)&Bs[k][tx * 4];
            *(float4*)&b[4] = *(const float4*)&Bs[k][64 + tx * 4];
#pragma unroll
            for (int i = 0; i < 8; i++)
#pragma unroll
                for (int j = 0; j < 8; j++)
                    acc[i][j] += a[i] * b[j];
        }
        __syncthreads();
    }

    // epilogue
#pragma unroll
    for (int i = 0; i < 8; i++) {
        int r = rowBase + ((i < 4) ? (ty * 4 + i) : (64 + ty * 4 + (i - 4)));
#pragma unroll
        for (int jh = 0; jh < 2; jh++) {
            int c = colBase + jh * 64 + tx * 4;
            float4 bv = *(const float4*)(bias + c);
            float4 val;
            val.x = acc[i][jh * 4 + 0] + bv.x;
            val.y = acc[i][jh * 4 + 1] + bv.y;
            val.z = acc[i][jh * 4 + 2] + bv.z;
            val.w = acc[i][jh * 4 + 3] + bv.w;
            if (headmajor) {
                int nn = r >> 10, ss = r & 1023, hh = c >> 6, dd = c & 63;
                *(float4*)(out + ((size_t)((nn * HH + hh) * SQ + ss)) * DK + dd) = val;
            } else {
                *(float4*)(out + (size_t)r * Ndim + c) = val;
            }
        }
    }
}

// -------------------- fused masked-softmax attention --------------------------
// grid: (S/64 q-tiles, H, N); 256 threads; BLOCK_Q = BLOCK_K = 64.
// Qst/Kst: transposed [d][row] with XOR-swizzled row-blocks.
// P tile aliases the K tile (K dead after logits). Online softmax.
__global__ void __launch_bounds__(256) attn_kernel(
    const float* __restrict__ Q, const float* __restrict__ K, const float* __restrict__ V,
    const unsigned char* __restrict__ mask8, float* __restrict__ O)
{
    __shared__ float Qst[64][64];
    __shared__ float KP[64][64];   // Kst, aliased as Ps
    __shared__ float Vs[64][64];

    const int tid = threadIdx.x;
    const int tx = tid & 15, ty = tid >> 4;
    const int qt = blockIdx.x, h = blockIdx.y, n = blockIdx.z;
    const float scale = 0.125f;   // 1/sqrt(64)

    const float* Qbase = Q + ((size_t)(n * HH + h) * SQ + qt * 64) * DK;
    const float* Kbase = K + ((size_t)(n * HH + h) * SQ) * DK;
    const float* Vbase = V + ((size_t)(n * HH + h) * SQ) * DK;
    const unsigned char* Mbase = mask8 + ((size_t)(n * SQ) + qt * 64) * SQ;

    // load Q transposed + swizzled (1024 float4s, 4/thread)
#pragma unroll
    for (int p = 0; p < 4; p++) {
        int f = tid + p * 256;
        int r = f >> 4;            // q row 0..63
        int d4 = f & 15;
        float4 v = *(const float4*)(Qbase + r * DK + d4 * 4);
        float vals[4] = {v.x, v.y, v.z, v.w};
#pragma unroll
        for (int c = 0; c < 4; c++) {
            int d = d4 * 4 + c;
            Qst[d][(((r >> 2) ^ (d & 15)) << 2) + (r & 3)] = vals[c];
        }
    }

    float m[4], l[4], o[4][4];
#pragma unroll
    for (int i = 0; i < 4; i++) {
        m[i] = -1e30f; l[i] = 0.0f;
#pragma unroll
        for (int j = 0; j < 4; j++) o[i][j] = 0.0f;
    }

    for (int kt = 0; kt < SQ / 64; kt++) {
        __syncthreads();   // also covers Qst visibility on first iter
        // load K (transposed+swizzled) and V (natural)
#pragma unroll
        for (int p = 0; p < 4; p++) {
            int f = tid + p * 256;
            int r = f >> 4;
            int d4 = f & 15;
            float4 kv4 = *(const float4*)(Kbase + (size_t)(kt * 64 + r) * DK + d4 * 4);
            float kvals[4] = {kv4.x, kv4.y, kv4.z, kv4.w};
#pragma unroll
            for (int c = 0; c < 4; c++) {
                int d = d4 * 4 + c;
                KP[d][(((r >> 2) ^ (d & 15)) << 2) + (r & 3)] = kvals[c];
            }
            float4 vv4 = *(const float4*)(Vbase + (size_t)(kt * 64 + r) * DK + d4 * 4);
            *(float4*)&Vs[r][d4 * 4] = vv4;
        }
        __syncthreads();

        // logits: s[i][j] = q(4ty+i) . k(4tx+j)
        float s[4][4];
#pragma unroll
        for (int i = 0; i < 4; i++)
#pragma unroll
            for (int j = 0; j < 4; j++) s[i][j] = 0.0f;

#pragma unroll 8
        for (int d = 0; d < 64; d++) {
            int sw = d & 15;
            float4 qv = *(const float4*)&Qst[d][((ty ^ sw) << 2)];
            float4 kv = *(const float4*)&KP[d][((tx ^ sw) << 2)];
            float qa[4] = {qv.x, qv.y, qv.z, qv.w};
            float ka[4] = {kv.x, kv.y, kv.z, kv.w};
#pragma unroll
            for (int i = 0; i < 4; i++)
#pragma unroll
                for (int j = 0; j < 4; j++)
                    s[i][j] += qa[i] * ka[j];
        }

        // scale + mask
#pragma unroll
        for (int i = 0; i < 4; i++) {
            int q = 4 * ty + i;
            uchar4 mk = *(const uchar4*)(Mbase + (size_t)q * SQ + kt * 64 + 4 * tx);
            s[i][0] = mk.x ? -1e9f : s[i][0] * scale;
            s[i][1] = mk.y ? -1e9f : s[i][1] * scale;
            s[i][2] = mk.z ? -1e9f : s[i][2] * scale;
            s[i][3] = mk.w ? -1e9f : s[i][3] * scale;
        }

        // online softmax update
        float rmax[4], rsum[4];
#pragma unroll
        for (int i = 0; i < 4; i++) {
            float v = fmaxf(fmaxf(s[i][0], s[i][1]), fmaxf(s[i][2], s[i][3]));
#pragma unroll
            for (int off = 1; off < 16; off <<= 1)
                v = fmaxf(v, __shfl_xor_sync(0xffffffffu, v, off, 16));
            rmax[i] = v;
        }
#pragma unroll
        for (int i = 0; i < 4; i++) {
            float mn = fmaxf(m[i], rmax[i]);
            float alpha = __expf(m[i] - mn);
            m[i] = mn;
            float ps = 0.0f;
#pragma unroll
            for (int j = 0; j < 4; j++) {
                s[i][j] = __expf(s[i][j] - mn);   // s becomes p
                ps += s[i][j];
            }
#pragma unroll
            for (int off = 1; off < 16; off <<= 1)
                ps += __shfl_xor_sync(0xffffffffu, ps, off, 16);
            rsum[i] = ps;
            l[i] = l[i] * alpha + rsum[i];
#pragma unroll
            for (int j = 0; j < 4; j++) o[i][j] *= alpha;
        }

        __syncthreads();   // everyone done reading KP (K) before overwrite with P
        float (*Ps)[64] = KP;
#pragma unroll
        for (int i = 0; i < 4; i++) {
            float4 pv = make_float4(s[i][0], s[i][1], s[i][2], s[i][3]);
            *(float4*)&Ps[4 * ty + i][4 * tx] = pv;
        }
        __syncthreads();

        // O += P @ V : o[i][dd], dd cols = 4tx..4tx+3
#pragma unroll 4
        for (int j4 = 0; j4 < 16; j4++) {
            float4 pa[4], va[4];
#pragma unroll
            for (int i = 0; i < 4; i++) pa[i] = *(const float4*)&Ps[4 * ty + i][4 * j4];
#pragma unroll
            for (int jj = 0; jj < 4; jj++) va[jj] = *(const float4*)&Vs[4 * j4 + jj][4 * tx];
#pragma unroll
            for (int i = 0; i < 4; i++) {
                const float* pf = (const float*)&pa[i];
#pragma unroll
                for (int jj = 0; jj < 4; jj++) {
                    float pv = pf[jj];
                    o[i][0] += pv * va[jj].x;
                    o[i][1] += pv * va[jj].y;
                    o[i][2] += pv * va[jj].z;
                    o[i][3] += pv * va[jj].w;
                }
            }
        }
    }

    // write O to [n, s, e] layout (e = h*64 + d)
#pragma unroll
    for (int i = 0; i < 4; i++) {
        float inv = 1.0f / l[i];
        int q = qt * 64 + 4 * ty + i;
        float4 val = make_float4(o[i][0] * inv, o[i][1] * inv, o[i][2] * inv, o[i][3] * inv);
        *(float4*)(O + ((size_t)(n * SQ + q)) * EE + h * DK + 4 * tx) = val;
    }
}

// -------------------- launch ---------------------------------------------------
extern "C" void kernel_launch(void* const* d_in, const int* in_sizes, int n_in,
                              void* d_out, int out_size)
{
    const float* x    = (const float*)d_in[0];
    const void*  mask = d_in[1];
    const float* Wq   = (const float*)d_in[2];
    const float* bq   = (const float*)d_in[3];
    const float* Wk   = (const float*)d_in[4];
    const float* bk   = (const float*)d_in[5];
    const float* Wv   = (const float*)d_in[6];
    const float* bv   = (const float*)d_in[7];
    const float* Wo   = (const float*)d_in[8];
    const float* bo   = (const float*)d_in[9];
    float* out = (float*)d_out;

    float *q, *k, *v, *ao;
    cudaGetSymbolAddress((void**)&q,  g_q);
    cudaGetSymbolAddress((void**)&k,  g_k);
    cudaGetSymbolAddress((void**)&v,  g_v);
    cudaGetSymbolAddress((void**)&ao, g_ao);
    unsigned char* m8;
    cudaGetSymbolAddress((void**)&m8, g_mask8);

    // 1. mask dtype detect + convert to u8
    detect_mask_kernel<<<1, 256>>>((const unsigned int*)mask);
    int nmask = NB * SQ * SQ;
    convert_mask_kernel<<<(nmask + 255) / 256, 256>>>(mask, nmask);

    // 2. fused QKV projections, head-major output
    dim3 gq(EE / 128, (NB * SQ) / 128, 3);
    gemm_bias_kernel<<<gq, 256>>>(x, Wq, Wk, Wv, bq, bk, bv, q, k, v, 1);

    // 3. attention
    dim3 ga(SQ / 64, HH, NB);
    attn_kernel<<<ga, 256>>>(q, k, v, m8, ao);

    // 4. output projection
    dim3 go(EE / 128, (NB * SQ) / 128, 1);
    gemm_bias_kernel<<<go, 256>>>(ao, Wo, Wo, Wo, bo, bo, bo, out, out, out, 0);
}

// round 3
// speedup vs baseline: 2.5625x; 2.5625x over previous
#include <cuda_runtime.h>
#include <cuda_bf16.h>
#include <cstdint>

// Problem dims
#define NB   8
#define SQ   1024
#define EE   1024
#define HH   16
#define DK   64

// -------------------- scratch (static device arrays; no allocation) -----------
__device__ float g_q[NB * HH * SQ * DK];     // [n,h,s,d]
__device__ float g_k[NB * HH * SQ * DK];
__device__ float g_v[NB * HH * SQ * DK];
__device__ float g_ao[NB * SQ * EE];         // attention output, [n,s,e]
__device__ unsigned char g_mask8[NB * SQ * SQ];
__device__ int g_mask_fmt;                   // 0=i32, 1=f32, 2=u8

__device__ __nv_bfloat16 g_xh[NB * SQ * EE];     // x hi/lo bf16
__device__ __nv_bfloat16 g_xl[NB * SQ * EE];
__device__ __nv_bfloat16 g_wth[4 * EE * EE];     // W^T hi/lo bf16, [n][k], 4 mats
__device__ __nv_bfloat16 g_wtl[4 * EE * EE];
__device__ __nv_bfloat16 g_aoh[NB * SQ * EE];    // attn-out hi/lo bf16
__device__ __nv_bfloat16 g_aol[NB * SQ * EE];

// -------------------- helpers --------------------------------------------------
__device__ __forceinline__ uint32_t smem_u32(const void* p) {
    uint32_t a;
    asm("{ .reg .u64 t; cvta.to.shared.u64 t, %1; cvt.u32.u64 %0, t; }" : "=r"(a) : "l"(p));
    return a;
}
__device__ __forceinline__ void cp_async16(uint32_t dst, const void* src) {
    asm volatile("cp.async.cg.shared.global [%0], [%1], 16;" :: "r"(dst), "l"(src));
}
#define CP_COMMIT() asm volatile("cp.async.commit_group;" ::: "memory")
#define CP_WAIT1()  asm volatile("cp.async.wait_group 1;" ::: "memory")

__device__ __forceinline__ void ldsm4(uint32_t* r, uint32_t addr) {
    asm volatile("ldmatrix.sync.aligned.m8n8.x4.shared.b16 {%0,%1,%2,%3}, [%4];"
        : "=r"(r[0]), "=r"(r[1]), "=r"(r[2]), "=r"(r[3]) : "r"(addr));
}
__device__ __forceinline__ void mma_bf16(float* c, const uint32_t* a, uint32_t b0, uint32_t b1) {
    asm volatile(
        "mma.sync.aligned.m16n8k16.row.col.f32.bf16.bf16.f32 "
        "{%0,%1,%2,%3}, {%4,%5,%6,%7}, {%8,%9}, {%0,%1,%2,%3};"
        : "+f"(c[0]), "+f"(c[1]), "+f"(c[2]), "+f"(c[3])
        : "r"(a[0]), "r"(a[1]), "r"(a[2]), "r"(a[3]), "r"(b0), "r"(b1));
}

// -------------------- mask dtype detection + conversion ----------------------
__global__ void detect_mask_kernel(const unsigned int* __restrict__ m) {
    __shared__ int s01, sf;
    if (threadIdx.x == 0) { s01 = 1; sf = 1; }
    __syncthreads();
    unsigned int v = m[threadIdx.x];
    if (v > 1u) s01 = 0;
    if (v != 0u && v != 0x3F800000u) sf = 0;
    __syncthreads();
    if (threadIdx.x == 0) g_mask_fmt = s01 ? 0 : (sf ? 1 : 2);
}

__global__ void convert_mask_kernel(const void* __restrict__ m, int n) {
    int i = blockIdx.x * blockDim.x + threadIdx.x;
    if (i >= n) return;
    int fmt = g_mask_fmt;
    unsigned char v;
    if (fmt == 0)      v = (((const int*)m)[i]   != 0)    ? 1 : 0;
    else if (fmt == 1) v = (((const float*)m)[i] != 0.0f) ? 1 : 0;
    else               v = (((const unsigned char*)m)[i] != 0) ? 1 : 0;
    g_mask8[i] = v;
}

// -------------------- fp32 -> bf16 hi/lo split (elementwise) ------------------
__global__ void split_kernel(const float* __restrict__ in,
                             __nv_bfloat16* __restrict__ oh,
                             __nv_bfloat16* __restrict__ ol) {
    int i = blockIdx.x * blockDim.x + threadIdx.x;   // float4 index
    float4 v = ((const float4*)in)[i];
    __nv_bfloat16 h0 = __float2bfloat16(v.x), h1 = __float2bfloat16(v.y);
    __nv_bfloat16 h2 = __float2bfloat16(v.z), h3 = __float2bfloat16(v.w);
    float l0 = v.x - __bfloat162float(h0), l1 = v.y - __bfloat162float(h1);
    float l2 = v.z - __bfloat162float(h2), l3 = v.w - __bfloat162float(h3);
    __nv_bfloat162* oh2 = (__nv_bfloat162*)oh;
    __nv_bfloat162* ol2 = (__nv_bfloat162*)ol;
    oh2[i * 2]     = __nv_bfloat162(h0, h1);
    oh2[i * 2 + 1] = __nv_bfloat162(h2, h3);
    ol2[i * 2]     = __floats2bfloat162_rn(l0, l1);
    ol2[i * 2 + 1] = __floats2bfloat162_rn(l2, l3);
}

// -------------------- W -> W^T hi/lo bf16 (transpose + split) -----------------
__global__ void convert_wt_kernel(const float* __restrict__ W0, const float* __restrict__ W1,
                                  const float* __restrict__ W2, const float* __restrict__ W3,
                                  __nv_bfloat16* __restrict__ wth, __nv_bfloat16* __restrict__ wtl) {
    const float* W = (blockIdx.z == 0) ? W0 : (blockIdx.z == 1) ? W1 : (blockIdx.z == 2) ? W2 : W3;
    __shared__ float t[32][33];
    int tx = threadIdx.x, ty = threadIdx.y;          // 32 x 8
    int k0 = blockIdx.y * 32, n0 = blockIdx.x * 32;
#pragma unroll
    for (int j = 0; j < 4; j++)
        t[ty + 8 * j][tx] = W[(size_t)(k0 + ty + 8 * j) * EE + n0 + tx];
    __syncthreads();
    size_t off = (size_t)blockIdx.z << 20;
#pragma unroll
    for (int j = 0; j < 4; j++) {
        float f = t[tx][ty + 8 * j];
        __nv_bfloat16 h = __float2bfloat16(f);
        size_t o = off + (size_t)(n0 + ty + 8 * j) * EE + k0 + tx;
        wth[o] = h;
        wtl[o] = __float2bfloat16(f - __bfloat162float(h));
    }
}

// -------------------- mma.sync split-bf16 GEMM --------------------------------
// C[128,128] tile = A[128x1024] @ B[128x1024]^T, A/B bf16 hi/lo (K-major rows).
// D += Ah*Bh + Al*Bh + Ah*Bl. 8 warps (2M x 4N), warp tile 64x32.
// KC=64 per stage; 4 tiles (Ah,Al,Bh,Bl) of 128x64 bf16 = 16KB each, SW128
// swizzle; 3-stage cp.async pipeline (192KB smem, 1 CTA/SM).
#define TSZ        16384
#define STAGE_B    (4 * TSZ)
#define GEMM_SMEM  (3 * STAGE_B)
#define NKC        16            // 1024 / 64

__device__ __forceinline__ void load_stage(
    uint32_t sb, const __nv_bfloat16* ah, const __nv_bfloat16* al,
    const __nv_bfloat16* bh, const __nv_bfloat16* bl, int kc, int tid)
{
    const __nv_bfloat16* bases[4] = {ah, al, bh, bl};
#pragma unroll
    for (int t4 = 0; t4 < 4; t4++) {
        const __nv_bfloat16* base = bases[t4] + kc * 64;
        uint32_t dtile = sb + t4 * TSZ;
#pragma unroll
        for (int p = 0; p < 4; p++) {
            int idx = p * 256 + tid;
            int r = idx >> 3, c = idx & 7;
            cp_async16(dtile + r * 128 + (((c ^ (r & 7))) << 4),
                       base + (size_t)r * EE + c * 8);
        }
    }
}

__global__ void __launch_bounds__(256) gemm_mma_kernel(
    const __nv_bfloat16* __restrict__ Ah, const __nv_bfloat16* __restrict__ Al,
    const __nv_bfloat16* __restrict__ Wh, const __nv_bfloat16* __restrict__ Wl,
    const float* __restrict__ b0, const float* __restrict__ b1, const float* __restrict__ b2,
    float* o0, float* o1, float* o2, int headmajor, int wbase)
{
    extern __shared__ char smem[];
    const uint32_t sbase = smem_u32(smem);
    const int tid = threadIdx.x;
    const int z = blockIdx.z;
    const float* bias = (z == 0) ? b0 : (z == 1) ? b1 : b2;
    float* out = (z == 0) ? o0 : (z == 1) ? o1 : o2;
    const size_t woff = ((size_t)(wbase + z)) << 20;

    const int mBase = blockIdx.y * 128;
    const int nBase = blockIdx.x * 128;
    const __nv_bfloat16* ah = Ah + (size_t)mBase * EE;
    const __nv_bfloat16* al = Al + (size_t)mBase * EE;
    const __nv_bfloat16* bh = Wh + woff + (size_t)nBase * EE;
    const __nv_bfloat16* bl = Wl + woff + (size_t)nBase * EE;

    // prologue: stages 0,1
    load_stage(sbase + 0 * STAGE_B, ah, al, bh, bl, 0, tid);
    CP_COMMIT();
    load_stage(sbase + 1 * STAGE_B, ah, al, bh, bl, 1, tid);
    CP_COMMIT();

    const int lane = tid & 31;
    const int wm = (tid >> 5) & 1;     // 0..1
    const int wn = tid >> 6;           // 0..3
    const int l15 = lane & 15, l16 = lane >> 4;

    float c[4][4][4];
#pragma unroll
    for (int i = 0; i < 4; i++)
#pragma unroll
        for (int j = 0; j < 4; j++)
#pragma unroll
            for (int q = 0; q < 4; q++) c[i][j][q] = 0.0f;

    for (int kc = 0; kc < NKC; kc++) {
        CP_WAIT1();
        __syncthreads();
        if (kc + 2 < NKC)
            load_stage(sbase + ((kc + 2) % 3) * STAGE_B, ah, al, bh, bl, kc + 2, tid);
        CP_COMMIT();

        const uint32_t sb = sbase + (kc % 3) * STAGE_B;
#pragma unroll
        for (int ko = 0; ko < 4; ko++) {
            uint32_t a[4][4], bh0[4], bh1[4], bl0[4], bl1[4];
            const int ch = ko * 2 + l16;
            // A hi frags (rows wm*64 + i*16 + l15)
#pragma unroll
            for (int i = 0; i < 4; i++) {
                int r = wm * 64 + i * 16 + l15;
                ldsm4(a[i], sb + r * 128 + ((ch ^ (r & 7)) << 4));
            }
            // B hi frags (rows wn*32 + {0,16} + l15)
            {
                int r0 = wn * 32 + l15;
                ldsm4(bh0, sb + 2 * TSZ + r0 * 128 + ((ch ^ (r0 & 7)) << 4));
                int r1 = wn * 32 + 16 + l15;
                ldsm4(bh1, sb + 2 * TSZ + r1 * 128 + ((ch ^ (r1 & 7)) << 4));
                ldsm4(bl0, sb + 3 * TSZ + r0 * 128 + ((ch ^ (r0 & 7)) << 4));
                ldsm4(bl1, sb + 3 * TSZ + r1 * 128 + ((ch ^ (r1 & 7)) << 4));
            }
            // Ah*Bh + Ah*Bl
#pragma unroll
            for (int i = 0; i < 4; i++) {
                mma_bf16(c[i][0], a[i], bh0[0], bh0[2]);
                mma_bf16(c[i][1], a[i], bh0[1], bh0[3]);
                mma_bf16(c[i][2], a[i], bh1[0], bh1[2]);
                mma_bf16(c[i][3], a[i], bh1[1], bh1[3]);
                mma_bf16(c[i][0], a[i], bl0[0], bl0[2]);
                mma_bf16(c[i][1], a[i], bl0[1], bl0[3]);
                mma_bf16(c[i][2], a[i], bl1[0], bl1[2]);
                mma_bf16(c[i][3], a[i], bl1[1], bl1[3]);
            }
            // Al (reuse a regs), then Al*Bh
#pragma unroll
            for (int i = 0; i < 4; i++) {
                int r = wm * 64 + i * 16 + l15;
                ldsm4(a[i], sb + TSZ + r * 128 + ((ch ^ (r & 7)) << 4));
            }
#pragma unroll
            for (int i = 0; i < 4; i++) {
                mma_bf16(c[i][0], a[i], bh0[0], bh0[2]);
                mma_bf16(c[i][1], a[i], bh0[1], bh0[3]);
                mma_bf16(c[i][2], a[i], bh1[0], bh1[2]);
                mma_bf16(c[i][3], a[i], bh1[1], bh1[3]);
            }
        }
    }

    // epilogue: bias add + store
    const int lr = lane >> 2, lc = lane & 3;
#pragma unroll
    for (int i = 0; i < 4; i++) {
#pragma unroll
        for (int half = 0; half < 2; half++) {
            const int R = mBase + wm * 64 + i * 16 + half * 8 + lr;
#pragma unroll
            for (int j = 0; j < 4; j++) {
                const int C0 = nBase + wn * 32 + j * 8 + lc * 2;
                float2 bv = *(const float2*)(bias + C0);
                float2 val = make_float2(c[i][j][half * 2 + 0] + bv.x,
                                         c[i][j][half * 2 + 1] + bv.y);
                if (headmajor) {
                    const int nidx = R >> 10, sidx = R & 1023;
                    const int head = C0 >> 6, dd = C0 & 63;
                    *(float2*)(out + (((size_t)(nidx * HH + head) * SQ + sidx) << 6) + dd) = val;
                } else {
                    *(float2*)(out + (size_t)R * EE + C0) = val;
                }
            }
        }
    }
}

// -------------------- fused masked-softmax attention (R1, proven) --------------
__global__ void __launch_bounds__(256) attn_kernel(
    const float* __restrict__ Q, const float* __restrict__ K, const float* __restrict__ V,
    const unsigned char* __restrict__ mask8, float* __restrict__ O)
{
    __shared__ float Qst[64][64];
    __shared__ float KP[64][64];
    __shared__ float Vs[64][64];

    const int tid = threadIdx.x;
    const int tx = tid & 15, ty = tid >> 4;
    const int qt = blockIdx.x, h = blockIdx.y, n = blockIdx.z;
    const float scale = 0.125f;

    const float* Qbase = Q + ((size_t)(n * HH + h) * SQ + qt * 64) * DK;
    const float* Kbase = K + ((size_t)(n * HH + h) * SQ) * DK;
    const float* Vbase = V + ((size_t)(n * HH + h) * SQ) * DK;
    const unsigned char* Mbase = mask8 + ((size_t)(n * SQ) + qt * 64) * SQ;

#pragma unroll
    for (int p = 0; p < 4; p++) {
        int f = tid + p * 256;
        int r = f >> 4;
        int d4 = f & 15;
        float4 v = *(const float4*)(Qbase + r * DK + d4 * 4);
        float vals[4] = {v.x, v.y, v.z, v.w};
#pragma unroll
        for (int c = 0; c < 4; c++) {
            int d = d4 * 4 + c;
            Qst[d][(((r >> 2) ^ (d & 15)) << 2) + (r & 3)] = vals[c];
        }
    }

    float m[4], l[4], o[4][4];
#pragma unroll
    for (int i = 0; i < 4; i++) {
        m[i] = -1e30f; l[i] = 0.0f;
#pragma unroll
        for (int j = 0; j < 4; j++) o[i][j] = 0.0f;
    }

    for (int kt = 0; kt < SQ / 64; kt++) {
        __syncthreads();
#pragma unroll
        for (int p = 0; p < 4; p++) {
            int f = tid + p * 256;
            int r = f >> 4;
            int d4 = f & 15;
            float4 kv4 = *(const float4*)(Kbase + (size_t)(kt * 64 + r) * DK + d4 * 4);
            float kvals[4] = {kv4.x, kv4.y, kv4.z, kv4.w};
#pragma unroll
            for (int c = 0; c < 4; c++) {
                int d = d4 * 4 + c;
                KP[d][(((r >> 2) ^ (d & 15)) << 2) + (r & 3)] = kvals[c];
            }
            float4 vv4 = *(const float4*)(Vbase + (size_t)(kt * 64 + r) * DK + d4 * 4);
            *(float4*)&Vs[r][d4 * 4] = vv4;
        }
        __syncthreads();

        float s[4][4];
#pragma unroll
        for (int i = 0; i < 4; i++)
#pragma unroll
            for (int j = 0; j < 4; j++) s[i][j] = 0.0f;

#pragma unroll 8
        for (int d = 0; d < 64; d++) {
            int sw = d & 15;
            float4 qv = *(const float4*)&Qst[d][((ty ^ sw) << 2)];
            float4 kv = *(const float4*)&KP[d][((tx ^ sw) << 2)];
            float qa[4] = {qv.x, qv.y, qv.z, qv.w};
            float ka[4] = {kv.x, kv.y, kv.z, kv.w};
#pragma unroll
            for (int i = 0; i < 4; i++)
#pragma unroll
                for (int j = 0; j < 4; j++)
                    s[i][j] += qa[i] * ka[j];
        }

#pragma unroll
        for (int i = 0; i < 4; i++) {
            int q = 4 * ty + i;
            uchar4 mk = *(const uchar4*)(Mbase + (size_t)q * SQ + kt * 64 + 4 * tx);
            s[i][0] = mk.x ? -1e9f : s[i][0] * scale;
            s[i][1] = mk.y ? -1e9f : s[i][1] * scale;
            s[i][2] = mk.z ? -1e9f : s[i][2] * scale;
            s[i][3] = mk.w ? -1e9f : s[i][3] * scale;
        }

        float rmax[4], rsum[4];
#pragma unroll
        for (int i = 0; i < 4; i++) {
            float v = fmaxf(fmaxf(s[i][0], s[i][1]), fmaxf(s[i][2], s[i][3]));
#pragma unroll
            for (int off = 1; off < 16; off <<= 1)
                v = fmaxf(v, __shfl_xor_sync(0xffffffffu, v, off, 16));
            rmax[i] = v;
        }
#pragma unroll
        for (int i = 0; i < 4; i++) {
            float mn = fmaxf(m[i], rmax[i]);
            float alpha = __expf(m[i] - mn);
            m[i] = mn;
            float ps = 0.0f;
#pragma unroll
            for (int j = 0; j < 4; j++) {
                s[i][j] = __expf(s[i][j] - mn);
                ps += s[i][j];
            }
#pragma unroll
            for (int off = 1; off < 16; off <<= 1)
                ps += __shfl_xor_sync(0xffffffffu, ps, off, 16);
            rsum[i] = ps;
            l[i] = l[i] * alpha + rsum[i];
#pragma unroll
            for (int j = 0; j < 4; j++) o[i][j] *= alpha;
        }

        __syncthreads();
        float (*Ps)[64] = KP;
#pragma unroll
        for (int i = 0; i < 4; i++) {
            float4 pv = make_float4(s[i][0], s[i][1], s[i][2], s[i][3]);
            *(float4*)&Ps[4 * ty + i][4 * tx] = pv;
        }
        __syncthreads();

#pragma unroll 4
        for (int j4 = 0; j4 < 16; j4++) {
            float4 pa[4], va[4];
#pragma unroll
            for (int i = 0; i < 4; i++) pa[i] = *(const float4*)&Ps[4 * ty + i][4 * j4];
#pragma unroll
            for (int jj = 0; jj < 4; jj++) va[jj] = *(const float4*)&Vs[4 * j4 + jj][4 * tx];
#pragma unroll
            for (int i = 0; i < 4; i++) {
                const float* pf = (const float*)&pa[i];
#pragma unroll
                for (int jj = 0; jj < 4; jj++) {
                    float pv = pf[jj];
                    o[i][0] += pv * va[jj].x;
                    o[i][1] += pv * va[jj].y;
                    o[i][2] += pv * va[jj].z;
                    o[i][3] += pv * va[jj].w;
                }
            }
        }
    }

#pragma unroll
    for (int i = 0; i < 4; i++) {
        float inv = 1.0f / l[i];
        int q = qt * 64 + 4 * ty + i;
        float4 val = make_float4(o[i][0] * inv, o[i][1] * inv, o[i][2] * inv, o[i][3] * inv);
        *(float4*)(O + ((size_t)(n * SQ + q)) * EE + h * DK + 4 * tx) = val;
    }
}

// -------------------- launch ---------------------------------------------------
extern "C" void kernel_launch(void* const* d_in, const int* in_sizes, int n_in,
                              void* d_out, int out_size)
{
    const float* x    = (const float*)d_in[0];
    const void*  mask = d_in[1];
    const float* Wq   = (const float*)d_in[2];
    const float* bq   = (const float*)d_in[3];
    const float* Wk   = (const float*)d_in[4];
    const float* bk   = (const float*)d_in[5];
    const float* Wv   = (const float*)d_in[6];
    const float* bv   = (const float*)d_in[7];
    const float* Wo   = (const float*)d_in[8];
    const float* bo   = (const float*)d_in[9];
    float* out = (float*)d_out;

    float *q, *k, *v, *ao;
    cudaGetSymbolAddress((void**)&q,  g_q);
    cudaGetSymbolAddress((void**)&k,  g_k);
    cudaGetSymbolAddress((void**)&v,  g_v);
    cudaGetSymbolAddress((void**)&ao, g_ao);
    unsigned char* m8;
    cudaGetSymbolAddress((void**)&m8, g_mask8);
    __nv_bfloat16 *xh, *xl, *wth, *wtl, *aoh, *aol;
    cudaGetSymbolAddress((void**)&xh,  g_xh);
    cudaGetSymbolAddress((void**)&xl,  g_xl);
    cudaGetSymbolAddress((void**)&wth, g_wth);
    cudaGetSymbolAddress((void**)&wtl, g_wtl);
    cudaGetSymbolAddress((void**)&aoh, g_aoh);
    cudaGetSymbolAddress((void**)&aol, g_aol);

    cudaFuncSetAttribute(gemm_mma_kernel,
                         cudaFuncAttributeMaxDynamicSharedMemorySize, GEMM_SMEM);

    // 1. mask detect + convert
    detect_mask_kernel<<<1, 256>>>((const unsigned int*)mask);
    int nmask = NB * SQ * SQ;
    convert_mask_kernel<<<(nmask + 255) / 256, 256>>>(mask, nmask);

    // 2. split x and W^T into bf16 hi/lo
    int nelem4 = NB * SQ * EE / 4;
    split_kernel<<<nelem4 / 256, 256>>>(x, xh, xl);
    convert_wt_kernel<<<dim3(32, 32, 4), dim3(32, 8)>>>(Wq, Wk, Wv, Wo, wth, wtl);

    // 3. QKV projections (tensor cores, head-major output)
    gemm_mma_kernel<<<dim3(EE / 128, NB * SQ / 128, 3), 256, GEMM_SMEM>>>(
        xh, xl, wth, wtl, bq, bk, bv, q, k, v, 1, 0);

    // 4. attention
    attn_kernel<<<dim3(SQ / 64, HH, NB), 256>>>(q, k, v, m8, ao);

    // 5. out projection (tensor cores)
    split_kernel<<<nelem4 / 256, 256>>>(ao, aoh, aol);
    gemm_mma_kernel<<<dim3(EE / 128, NB * SQ / 128, 1), 256, GEMM_SMEM>>>(
        aoh, aol, wth, wtl, bo, bo, bo, out, out, out, 0, 3);
}

// round 5
// speedup vs baseline: 4.1350x; 1.6136x over previous
#include <cuda_runtime.h>
#include <cuda_bf16.h>
#include <cstdint>

// Problem dims
#define NB   8
#define SQ   1024
#define EE   1024
#define HH   16
#define DK   64

// -------------------- scratch (static device arrays; no allocation) -----------
__device__ unsigned char g_mask8[NB * SQ * SQ];
__device__ int g_mask_fmt;

__device__ __nv_bfloat16 g_xh[NB * SQ * EE];
__device__ __nv_bfloat16 g_xl[NB * SQ * EE];
__device__ __nv_bfloat16 g_wth[4 * EE * EE];     // W^T hi/lo, [n][k], 4 mats
__device__ __nv_bfloat16 g_wtl[4 * EE * EE];
__device__ __nv_bfloat16 g_qh[NB * HH * SQ * DK];   // [n,h,s,d] bf16 hi/lo
__device__ __nv_bfloat16 g_ql[NB * HH * SQ * DK];
__device__ __nv_bfloat16 g_kh[NB * HH * SQ * DK];
__device__ __nv_bfloat16 g_kl[NB * HH * SQ * DK];
__device__ __nv_bfloat16 g_vh[NB * HH * SQ * DK];
__device__ __nv_bfloat16 g_vl[NB * HH * SQ * DK];
__device__ __nv_bfloat16 g_aoh[NB * SQ * EE];    // attn-out hi/lo, [n,s,e]
__device__ __nv_bfloat16 g_aol[NB * SQ * EE];

// -------------------- helpers --------------------------------------------------
__device__ __forceinline__ uint32_t smem_u32(const void* p) {
    uint32_t a;
    asm("{ .reg .u64 t; cvta.to.shared.u64 t, %1; cvt.u32.u64 %0, t; }" : "=r"(a) : "l"(p));
    return a;
}
__device__ __forceinline__ void cp_async16(uint32_t dst, const void* src) {
    asm volatile("cp.async.cg.shared.global [%0], [%1], 16;" :: "r"(dst), "l"(src));
}
#define CP_COMMIT() asm volatile("cp.async.commit_group;" ::: "memory")
#define CP_WAIT1()  asm volatile("cp.async.wait_group 1;" ::: "memory")

__device__ __forceinline__ void ldsm4(uint32_t* r, uint32_t addr) {
    asm volatile("ldmatrix.sync.aligned.m8n8.x4.shared.b16 {%0,%1,%2,%3}, [%4];"
        : "=r"(r[0]), "=r"(r[1]), "=r"(r[2]), "=r"(r[3]) : "r"(addr));
}
__device__ __forceinline__ void ldsm4t(uint32_t* r, uint32_t addr) {
    asm volatile("ldmatrix.sync.aligned.m8n8.x4.trans.shared.b16 {%0,%1,%2,%3}, [%4];"
        : "=r"(r[0]), "=r"(r[1]), "=r"(r[2]), "=r"(r[3]) : "r"(addr));
}
__device__ __forceinline__ void mma_bf16(float* c, const uint32_t* a, uint32_t b0, uint32_t b1) {
    asm volatile(
        "mma.sync.aligned.m16n8k16.row.col.f32.bf16.bf16.f32 "
        "{%0,%1,%2,%3}, {%4,%5,%6,%7}, {%8,%9}, {%0,%1,%2,%3};"
        : "+f"(c[0]), "+f"(c[1]), "+f"(c[2]), "+f"(c[3])
        : "r"(a[0]), "r"(a[1]), "r"(a[2]), "r"(a[3]), "r"(b0), "r"(b1));
}
__device__ __forceinline__ uint32_t pack_bf16(float x, float y) {
    __nv_bfloat162 t = __floats2bfloat162_rn(x, y);
    return *(uint32_t*)&t;
}

// -------------------- mask dtype detection + conversion ----------------------
__global__ void detect_mask_kernel(const unsigned int* __restrict__ m) {
    __shared__ int s01, sf;
    if (threadIdx.x == 0) { s01 = 1; sf = 1; }
    __syncthreads();
    unsigned int v = m[threadIdx.x];
    if (v > 1u) s01 = 0;
    if (v != 0u && v != 0x3F800000u) sf = 0;
    __syncthreads();
    if (threadIdx.x == 0) g_mask_fmt = s01 ? 0 : (sf ? 1 : 2);
}

__global__ void convert_mask_kernel(const void* __restrict__ m, int n) {
    int i = blockIdx.x * blockDim.x + threadIdx.x;
    if (i >= n) return;
    int fmt = g_mask_fmt;
    unsigned char v;
    if (fmt == 0)      v = (((const int*)m)[i]   != 0)    ? 1 : 0;
    else if (fmt == 1) v = (((const float*)m)[i] != 0.0f) ? 1 : 0;
    else               v = (((const unsigned char*)m)[i] != 0) ? 1 : 0;
    g_mask8[i] = v;
}

// -------------------- fp32 -> bf16 hi/lo split (x only) ------------------------
__global__ void split_kernel(const float* __restrict__ in,
                             __nv_bfloat16* __restrict__ oh,
                             __nv_bfloat16* __restrict__ ol) {
    int i = blockIdx.x * blockDim.x + threadIdx.x;
    float4 v = ((const float4*)in)[i];
    __nv_bfloat16 h0 = __float2bfloat16(v.x), h1 = __float2bfloat16(v.y);
    __nv_bfloat16 h2 = __float2bfloat16(v.z), h3 = __float2bfloat16(v.w);
    float l0 = v.x - __bfloat162float(h0), l1 = v.y - __bfloat162float(h1);
    float l2 = v.z - __bfloat162float(h2), l3 = v.w - __bfloat162float(h3);
    __nv_bfloat162* oh2 = (__nv_bfloat162*)oh;
    __nv_bfloat162* ol2 = (__nv_bfloat162*)ol;
    oh2[i * 2]     = __nv_bfloat162(h0, h1);
    oh2[i * 2 + 1] = __nv_bfloat162(h2, h3);
    ol2[i * 2]     = __floats2bfloat162_rn(l0, l1);
    ol2[i * 2 + 1] = __floats2bfloat162_rn(l2, l3);
}

// -------------------- W -> W^T hi/lo bf16 --------------------------------------
__global__ void convert_wt_kernel(const float* __restrict__ W0, const float* __restrict__ W1,
                                  const float* __restrict__ W2, const float* __restrict__ W3,
                                  __nv_bfloat16* __restrict__ wth, __nv_bfloat16* __restrict__ wtl) {
    const float* W = (blockIdx.z == 0) ? W0 : (blockIdx.z == 1) ? W1 : (blockIdx.z == 2) ? W2 : W3;
    __shared__ float t[32][33];
    int tx = threadIdx.x, ty = threadIdx.y;
    int k0 = blockIdx.y * 32, n0 = blockIdx.x * 32;
#pragma unroll
    for (int j = 0; j < 4; j++)
        t[ty + 8 * j][tx] = W[(size_t)(k0 + ty + 8 * j) * EE + n0 + tx];
    __syncthreads();
    size_t off = (size_t)blockIdx.z << 20;
#pragma unroll
    for (int j = 0; j < 4; j++) {
        float f = t[tx][ty + 8 * j];
        __nv_bfloat16 h = __float2bfloat16(f);
        size_t o = off + (size_t)(n0 + ty + 8 * j) * EE + k0 + tx;
        wth[o] = h;
        wtl[o] = __float2bfloat16(f - __bfloat162float(h));
    }
}

// -------------------- mma.sync split-bf16 GEMM --------------------------------
#define TSZ        16384
#define STAGE_B    (4 * TSZ)
#define GEMM_SMEM  (3 * STAGE_B)
#define NKC        16

__device__ __forceinline__ void load_stage(
    uint32_t sb, const __nv_bfloat16* ah, const __nv_bfloat16* al,
    const __nv_bfloat16* bh, const __nv_bfloat16* bl, int kc, int tid)
{
    const __nv_bfloat16* bases[4] = {ah, al, bh, bl};
#pragma unroll
    for (int t4 = 0; t4 < 4; t4++) {
        const __nv_bfloat16* base = bases[t4] + kc * 64;
        uint32_t dtile = sb + t4 * TSZ;
#pragma unroll
        for (int p = 0; p < 4; p++) {
            int idx = p * 256 + tid;
            int r = idx >> 3, c = idx & 7;
            cp_async16(dtile + r * 128 + (((c ^ (r & 7))) << 4),
                       base + (size_t)r * EE + c * 8);
        }
    }
}

__global__ void __launch_bounds__(256) gemm_mma_kernel(
    const __nv_bfloat16* __restrict__ Ah, const __nv_bfloat16* __restrict__ Al,
    const __nv_bfloat16* __restrict__ Wh, const __nv_bfloat16* __restrict__ Wl,
    const float* __restrict__ b0, const float* __restrict__ b1, const float* __restrict__ b2,
    float* fo,
    __nv_bfloat16* oh0, __nv_bfloat16* oh1, __nv_bfloat16* oh2,
    __nv_bfloat16* ol0, __nv_bfloat16* ol1, __nv_bfloat16* ol2,
    int headmajor, int wbase)
{
    extern __shared__ char smem[];
    const uint32_t sbase = smem_u32(smem);
    const int tid = threadIdx.x;
    const int z = blockIdx.z;
    const float* bias = (z == 0) ? b0 : (z == 1) ? b1 : b2;
    __nv_bfloat16* oh = (z == 0) ? oh0 : (z == 1) ? oh1 : oh2;
    __nv_bfloat16* ol = (z == 0) ? ol0 : (z == 1) ? ol1 : ol2;
    const size_t woff = ((size_t)(wbase + z)) << 20;

    const int mBase = blockIdx.y * 128;
    const int nBase = blockIdx.x * 128;
    const __nv_bfloat16* ah = Ah + (size_t)mBase * EE;
    const __nv_bfloat16* al = Al + (size_t)mBase * EE;
    const __nv_bfloat16* bh = Wh + woff + (size_t)nBase * EE;
    const __nv_bfloat16* bl = Wl + woff + (size_t)nBase * EE;

    load_stage(sbase + 0 * STAGE_B, ah, al, bh, bl, 0, tid);
    CP_COMMIT();
    load_stage(sbase + 1 * STAGE_B, ah, al, bh, bl, 1, tid);
    CP_COMMIT();

    const int lane = tid & 31;
    const int wm = (tid >> 5) & 1;
    const int wn = tid >> 6;
    const int l15 = lane & 15, l16 = lane >> 4;

    float c[4][4][4];
#pragma unroll
    for (int i = 0; i < 4; i++)
#pragma unroll
        for (int j = 0; j < 4; j++)
#pragma unroll
            for (int q = 0; q < 4; q++) c[i][j][q] = 0.0f;

    for (int kc = 0; kc < NKC; kc++) {
        CP_WAIT1();
        __syncthreads();
        if (kc + 2 < NKC)
            load_stage(sbase + ((kc + 2) % 3) * STAGE_B, ah, al, bh, bl, kc + 2, tid);
        CP_COMMIT();

        const uint32_t sb = sbase + (kc % 3) * STAGE_B;
#pragma unroll
        for (int ko = 0; ko < 4; ko++) {
            uint32_t a[4][4], bh0[4], bh1[4], bl0[4], bl1[4];
            const int ch = ko * 2 + l16;
#pragma unroll
            for (int i = 0; i < 4; i++) {
                int r = wm * 64 + i * 16 + l15;
                ldsm4(a[i], sb + r * 128 + ((ch ^ (r & 7)) << 4));
            }
            {
                int r0 = wn * 32 + l15;
                ldsm4(bh0, sb + 2 * TSZ + r0 * 128 + ((ch ^ (r0 & 7)) << 4));
                int r1 = wn * 32 + 16 + l15;
                ldsm4(bh1, sb + 2 * TSZ + r1 * 128 + ((ch ^ (r1 & 7)) << 4));
                ldsm4(bl0, sb + 3 * TSZ + r0 * 128 + ((ch ^ (r0 & 7)) << 4));
                ldsm4(bl1, sb + 3 * TSZ + r1 * 128 + ((ch ^ (r1 & 7)) << 4));
            }
#pragma unroll
            for (int i = 0; i < 4; i++) {
                mma_bf16(c[i][0], a[i], bh0[0], bh0[2]);
                mma_bf16(c[i][1], a[i], bh0[1], bh0[3]);
                mma_bf16(c[i][2], a[i], bh1[0], bh1[2]);
                mma_bf16(c[i][3], a[i], bh1[1], bh1[3]);
                mma_bf16(c[i][0], a[i], bl0[0], bl0[2]);
                mma_bf16(c[i][1], a[i], bl0[1], bl0[3]);
                mma_bf16(c[i][2], a[i], bl1[0], bl1[2]);
                mma_bf16(c[i][3], a[i], bl1[1], bl1[3]);
            }
#pragma unroll
            for (int i = 0; i < 4; i++) {
                int r = wm * 64 + i * 16 + l15;
                ldsm4(a[i], sb + TSZ + r * 128 + ((ch ^ (r & 7)) << 4));
            }
#pragma unroll
            for (int i = 0; i < 4; i++) {
                mma_bf16(c[i][0], a[i], bh0[0], bh0[2]);
                mma_bf16(c[i][1], a[i], bh0[1], bh0[3]);
                mma_bf16(c[i][2], a[i], bh1[0], bh1[2]);
                mma_bf16(c[i][3], a[i], bh1[1], bh1[3]);
            }
        }
    }

    const int lr = lane >> 2, lc = lane & 3;
#pragma unroll
    for (int i = 0; i < 4; i++) {
#pragma unroll
        for (int half = 0; half < 2; half++) {
            const int R = mBase + wm * 64 + i * 16 + half * 8 + lr;
#pragma unroll
            for (int j = 0; j < 4; j++) {
                const int C0 = nBase + wn * 32 + j * 8 + lc * 2;
                float2 bv = *(const float2*)(bias + C0);
                float vx = c[i][j][half * 2 + 0] + bv.x;
                float vy = c[i][j][half * 2 + 1] + bv.y;
                if (headmajor) {
                    const int nidx = R >> 10, sidx = R & 1023;
                    const int head = C0 >> 6, dd = C0 & 63;
                    size_t off = (((size_t)(nidx * HH + head) * SQ + sidx) << 6) + dd;
                    __nv_bfloat16 h0 = __float2bfloat16(vx), h1 = __float2bfloat16(vy);
                    __nv_bfloat162 hp(h0, h1);
                    __nv_bfloat162 lp = __floats2bfloat162_rn(vx - __bfloat162float(h0),
                                                              vy - __bfloat162float(h1));
                    *(__nv_bfloat162*)(oh + off) = hp;
                    *(__nv_bfloat162*)(ol + off) = lp;
                } else {
                    *(float2*)(fo + (size_t)R * EE + C0) = make_float2(vx, vy);
                }
            }
        }
    }
}

// -------------------- flash attention on mma.sync ------------------------------
// CTA: 128 q-rows x 1 head. 8 warps x 16 rows. K-tiles of 64.
// S = Qh*Kh + Ql*Kh + Qh*Kl ; O += Ph*Vh + Pl*Vh + Ph*Vl (online softmax).
// smem: Q hi/lo 32KB + 3 stages x (Kh,Kl,Vh,Vl) 32KB = 128KB.
#define AQ_L     16384
#define AST(s)   (32768 + (s) * 32768)
#define A_KL     8192
#define A_VH     16384
#define A_VL     24576
#define ATT_SMEM (32768 + 3 * 32768)

__device__ __forceinline__ void att_load_stage(
    uint32_t sb, int st, const __nv_bfloat16* kh, const __nv_bfloat16* kl,
    const __nv_bfloat16* vh, const __nv_bfloat16* vl, int kt, int tid)
{
    const __nv_bfloat16* bases[4] = {kh, kl, vh, vl};
#pragma unroll
    for (int t4 = 0; t4 < 4; t4++) {
        const __nv_bfloat16* base = bases[t4] + (size_t)kt * 64 * DK;
        uint32_t dtile = sb + AST(st) + t4 * 8192;
#pragma unroll
        for (int p = 0; p < 2; p++) {
            int idx = p * 256 + tid;
            int r = idx >> 3, c = idx & 7;
            cp_async16(dtile + r * 128 + ((c ^ (r & 7)) << 4), base + r * 64 + c * 8);
        }
    }
}

__global__ void __launch_bounds__(256) attn_mma_kernel(
    const __nv_bfloat16* __restrict__ Qh, const __nv_bfloat16* __restrict__ Ql,
    const __nv_bfloat16* __restrict__ Kh, const __nv_bfloat16* __restrict__ Kl,
    const __nv_bfloat16* __restrict__ Vh, const __nv_bfloat16* __restrict__ Vl,
    const unsigned char* __restrict__ mask8,
    __nv_bfloat16* __restrict__ Oh, __nv_bfloat16* __restrict__ Ol)
{
    extern __shared__ char smem[];
    const uint32_t sb = smem_u32(smem);
    const int tid = threadIdx.x;
    const int qt = blockIdx.x, h = blockIdx.y, n = blockIdx.z;

    const size_t hoff = (size_t)(n * HH + h) * SQ * DK;
    const __nv_bfloat16* qh = Qh + hoff + (size_t)qt * 128 * DK;
    const __nv_bfloat16* ql = Ql + hoff + (size_t)qt * 128 * DK;
    const __nv_bfloat16* kh = Kh + hoff;
    const __nv_bfloat16* kl = Kl + hoff;
    const __nv_bfloat16* vh = Vh + hoff;
    const __nv_bfloat16* vl = Vl + hoff;

    // Q hi/lo load (group 0, with stage 0)
#pragma unroll
    for (int p = 0; p < 4; p++) {
        int idx = p * 256 + tid;
        int r = idx >> 3, c = idx & 7;
        uint32_t sw = r * 128 + ((c ^ (r & 7)) << 4);
        cp_async16(sb + sw, qh + r * 64 + c * 8);
        cp_async16(sb + AQ_L + sw, ql + r * 64 + c * 8);
    }
    att_load_stage(sb, 0, kh, kl, vh, vl, 0, tid);
    CP_COMMIT();
    att_load_stage(sb, 1, kh, kl, vh, vl, 1, tid);
    CP_COMMIT();

    const int w = tid >> 5, lane = tid & 31;
    const int l15 = lane & 15, l16 = lane >> 4;
    const int lr = lane >> 2, lc = lane & 3;
    const int qg0 = qt * 128 + w * 16 + lr;   // global q row for c[..][0,1]
    const int qg1 = qg0 + 8;                  // for c[..][2,3]
    const unsigned char* M0 = mask8 + ((size_t)n * SQ + qg0) * SQ + 2 * lc;
    const unsigned char* M1 = mask8 + ((size_t)n * SQ + qg1) * SQ + 2 * lc;

    float o[8][4];
#pragma unroll
    for (int i = 0; i < 8; i++)
#pragma unroll
        for (int j = 0; j < 4; j++) o[i][j] = 0.0f;
    float m0 = -1e30f, m1 = -1e30f, l0 = 0.0f, l1 = 0.0f;

    for (int kt = 0; kt < 16; kt++) {
        CP_WAIT1();
        __syncthreads();
        if (kt + 2 < 16)
            att_load_stage(sb, (kt + 2) % 3, kh, kl, vh, vl, kt + 2, tid);
        CP_COMMIT();

        const uint32_t stg = sb + AST(kt % 3);

        // mask prefetch (L2 hits)
        unsigned short mk0[8], mk1[8];
#pragma unroll
        for (int nt = 0; nt < 8; nt++) {
            mk0[nt] = *(const unsigned short*)(M0 + kt * 64 + nt * 8);
            mk1[nt] = *(const unsigned short*)(M1 + kt * 64 + nt * 8);
        }

        // ---- S = Q K^T (split) ----
        float s[8][4];
#pragma unroll
        for (int i = 0; i < 8; i++)
#pragma unroll
            for (int j = 0; j < 4; j++) s[i][j] = 0.0f;

#pragma unroll
        for (int ko = 0; ko < 4; ko++) {
            const int ch = 2 * ko + l16;
            uint32_t aqh[4], aql[4];
            {
                int r = w * 16 + l15;
                uint32_t sw = r * 128 + ((ch ^ (r & 7)) << 4);
                ldsm4(aqh, sb + sw);
                ldsm4(aql, sb + AQ_L + sw);
            }
#pragma unroll
            for (int nt2 = 0; nt2 < 4; nt2++) {
                int rk = nt2 * 16 + l15;
                uint32_t sw = rk * 128 + ((ch ^ (rk & 7)) << 4);
                uint32_t kb[4], klb[4];
                ldsm4(kb,  stg + sw);
                ldsm4(klb, stg + A_KL + sw);
                mma_bf16(s[2 * nt2],     aqh, kb[0], kb[2]);
                mma_bf16(s[2 * nt2 + 1], aqh, kb[1], kb[3]);
                mma_bf16(s[2 * nt2],     aql, kb[0], kb[2]);
                mma_bf16(s[2 * nt2 + 1], aql, kb[1], kb[3]);
                mma_bf16(s[2 * nt2],     aqh, klb[0], klb[2]);
                mma_bf16(s[2 * nt2 + 1], aqh, klb[1], klb[3]);
            }
        }

        // ---- scale + mask ----
#pragma unroll
        for (int nt = 0; nt < 8; nt++) {
            s[nt][0] = (mk0[nt] & 0x00FF) ? -1e9f : s[nt][0] * 0.125f;
            s[nt][1] = (mk0[nt] & 0xFF00) ? -1e9f : s[nt][1] * 0.125f;
            s[nt][2] = (mk1[nt] & 0x00FF) ? -1e9f : s[nt][2] * 0.125f;
            s[nt][3] = (mk1[nt] & 0xFF00) ? -1e9f : s[nt][3] * 0.125f;
        }

        // ---- online softmax ----
        float vx0 = -1e30f, vx1 = -1e30f;
#pragma unroll
        for (int nt = 0; nt < 8; nt++) {
            vx0 = fmaxf(vx0, fmaxf(s[nt][0], s[nt][1]));
            vx1 = fmaxf(vx1, fmaxf(s[nt][2], s[nt][3]));
        }
        vx0 = fmaxf(vx0, __shfl_xor_sync(0xffffffffu, vx0, 1));
        vx0 = fmaxf(vx0, __shfl_xor_sync(0xffffffffu, vx0, 2));
        vx1 = fmaxf(vx1, __shfl_xor_sync(0xffffffffu, vx1, 1));
        vx1 = fmaxf(vx1, __shfl_xor_sync(0xffffffffu, vx1, 2));

        float mn0 = fmaxf(m0, vx0), mn1 = fmaxf(m1, vx1);
        float a0 = __expf(m0 - mn0), a1 = __expf(m1 - mn1);
        m0 = mn0; m1 = mn1;
        float sum0 = 0.0f, sum1 = 0.0f;
#pragma unroll
        for (int nt = 0; nt < 8; nt++) {
            s[nt][0] = __expf(s[nt][0] - mn0);
            s[nt][1] = __expf(s[nt][1] - mn0);
            s[nt][2] = __expf(s[nt][2] - mn1);
            s[nt][3] = __expf(s[nt][3] - mn1);
            sum0 += s[nt][0] + s[nt][1];
            sum1 += s[nt][2] + s[nt][3];
        }
        sum0 += __shfl_xor_sync(0xffffffffu, sum0, 1);
        sum0 += __shfl_xor_sync(0xffffffffu, sum0, 2);
        sum1 += __shfl_xor_sync(0xffffffffu, sum1, 1);
        sum1 += __shfl_xor_sync(0xffffffffu, sum1, 2);
        l0 = l0 * a0 + sum0;
        l1 = l1 * a1 + sum1;
#pragma unroll
        for (int nt = 0; nt < 8; nt++) {
            o[nt][0] *= a0; o[nt][1] *= a0;
            o[nt][2] *= a1; o[nt][3] *= a1;
        }

        // ---- O += P V (split) ----
#pragma unroll
        for (int t = 0; t < 4; t++) {
            // A-frags from P (C-fragment layout == A-fragment layout)
            uint32_t ph[4], pl[4];
            {
                float p0 = s[2 * t][0],     p1 = s[2 * t][1];
                float p2 = s[2 * t][2],     p3 = s[2 * t][3];
                float p4 = s[2 * t + 1][0], p5 = s[2 * t + 1][1];
                float p6 = s[2 * t + 1][2], p7 = s[2 * t + 1][3];
                __nv_bfloat16 h0 = __float2bfloat16(p0), h1 = __float2bfloat16(p1);
                __nv_bfloat16 h2 = __float2bfloat16(p2), h3 = __float2bfloat16(p3);
                __nv_bfloat16 h4 = __float2bfloat16(p4), h5 = __float2bfloat16(p5);
                __nv_bfloat16 h6 = __float2bfloat16(p6), h7 = __float2bfloat16(p7);
                __nv_bfloat162 t0(h0, h1), t1(h2, h3), t2(h4, h5), t3(h6, h7);
                ph[0] = *(uint32_t*)&t0; ph[1] = *(uint32_t*)&t1;
                ph[2] = *(uint32_t*)&t2; ph[3] = *(uint32_t*)&t3;
                pl[0] = pack_bf16(p0 - __bfloat162float(h0), p1 - __bfloat162float(h1));
                pl[1] = pack_bf16(p2 - __bfloat162float(h2), p3 - __bfloat162float(h3));
                pl[2] = pack_bf16(p4 - __bfloat162float(h4), p5 - __bfloat162float(h5));
                pl[3] = pack_bf16(p6 - __bfloat162float(h6), p7 - __bfloat162float(h7));
            }
#pragma unroll
            for (int dt2 = 0; dt2 < 4; dt2++) {
                int rv = t * 16 + l15;
                int chd = 2 * dt2 + l16;
                uint32_t sw = rv * 128 + ((chd ^ (rv & 7)) << 4);
                uint32_t vbh[4], vbl[4];
                ldsm4t(vbh, stg + A_VH + sw);
                ldsm4t(vbl, stg + A_VL + sw);
                mma_bf16(o[2 * dt2],     ph, vbh[0], vbh[1]);
                mma_bf16(o[2 * dt2 + 1], ph, vbh[2], vbh[3]);
                mma_bf16(o[2 * dt2],     pl, vbh[0], vbh[1]);
                mma_bf16(o[2 * dt2 + 1], pl, vbh[2], vbh[3]);
                mma_bf16(o[2 * dt2],     ph, vbl[0], vbl[1]);
                mma_bf16(o[2 * dt2 + 1], ph, vbl[2], vbl[3]);
            }
        }
    }

    // ---- epilogue: normalize, split to bf16 hi/lo, store [n,s,e] ----
    const float inv0 = 1.0f / l0, inv1 = 1.0f / l1;
    const size_t base0 = ((size_t)n * SQ + qg0) * EE + h * DK + 2 * lc;
    const size_t base1 = ((size_t)n * SQ + qg1) * EE + h * DK + 2 * lc;
#pragma unroll
    for (int nt = 0; nt < 8; nt++) {
        float vx = o[nt][0] * inv0, vy = o[nt][1] * inv0;
        __nv_bfloat16 h0 = __float2bfloat16(vx), h1 = __float2bfloat16(vy);
        __nv_bfloat162 hp(h0, h1);
        __nv_bfloat162 lp = __floats2bfloat162_rn(vx - __bfloat162float(h0),
                                                  vy - __bfloat162float(h1));
        *(__nv_bfloat162*)(Oh + base0 + nt * 8) = hp;
        *(__nv_bfloat162*)(Ol + base0 + nt * 8) = lp;

        vx = o[nt][2] * inv1; vy = o[nt][3] * inv1;
        h0 = __float2bfloat16(vx); h1 = __float2bfloat16(vy);
        __nv_bfloat162 hp1(h0, h1);
        __nv_bfloat162 lp1 = __floats2bfloat162_rn(vx - __bfloat162float(h0),
                                                   vy - __bfloat162float(h1));
        *(__nv_bfloat162*)(Oh + base1 + nt * 8) = hp1;
        *(__nv_bfloat162*)(Ol + base1 + nt * 8) = lp1;
    }
}

// -------------------- launch ---------------------------------------------------
extern "C" void kernel_launch(void* const* d_in, const int* in_sizes, int n_in,
                              void* d_out, int out_size)
{
    const float* x    = (const float*)d_in[0];
    const void*  mask = d_in[1];
    const float* Wq   = (const float*)d_in[2];
    const float* bq   = (const float*)d_in[3];
    const float* Wk   = (const float*)d_in[4];
    const float* bk   = (const float*)d_in[5];
    const float* Wv   = (const float*)d_in[6];
    const float* bv   = (const float*)d_in[7];
    const float* Wo   = (const float*)d_in[8];
    const float* bo   = (const float*)d_in[9];
    float* out = (float*)d_out;

    unsigned char* m8;
    cudaGetSymbolAddress((void**)&m8, g_mask8);
    __nv_bfloat16 *xh, *xl, *wth, *wtl, *aoh, *aol;
    __nv_bfloat16 *qh, *ql, *kh, *kl, *vh, *vl;
    cudaGetSymbolAddress((void**)&xh,  g_xh);
    cudaGetSymbolAddress((void**)&xl,  g_xl);
    cudaGetSymbolAddress((void**)&wth, g_wth);
    cudaGetSymbolAddress((void**)&wtl, g_wtl);
    cudaGetSymbolAddress((void**)&aoh, g_aoh);
    cudaGetSymbolAddress((void**)&aol, g_aol);
    cudaGetSymbolAddress((void**)&qh,  g_qh);
    cudaGetSymbolAddress((void**)&ql,  g_ql);
    cudaGetSymbolAddress((void**)&kh,  g_kh);
    cudaGetSymbolAddress((void**)&kl,  g_kl);
    cudaGetSymbolAddress((void**)&vh,  g_vh);
    cudaGetSymbolAddress((void**)&vl,  g_vl);

    cudaFuncSetAttribute(gemm_mma_kernel,
                         cudaFuncAttributeMaxDynamicSharedMemorySize, GEMM_SMEM);
    cudaFuncSetAttribute(attn_mma_kernel,
                         cudaFuncAttributeMaxDynamicSharedMemorySize, ATT_SMEM);

    // 1. mask detect + convert
    detect_mask_kernel<<<1, 256>>>((const unsigned int*)mask);
    int nmask = NB * SQ * SQ;
    convert_mask_kernel<<<(nmask + 255) / 256, 256>>>(mask, nmask);

    // 2. split x, build W^T hi/lo
    int nelem4 = NB * SQ * EE / 4;
    split_kernel<<<nelem4 / 256, 256>>>(x, xh, xl);
    convert_wt_kernel<<<dim3(32, 32, 4), dim3(32, 8)>>>(Wq, Wk, Wv, Wo, wth, wtl);

    // 3. QKV projections -> bf16 hi/lo head-major
    gemm_mma_kernel<<<dim3(EE / 128, NB * SQ / 128, 3), 256, GEMM_SMEM>>>(
        xh, xl, wth, wtl, bq, bk, bv, nullptr,
        qh, kh, vh, ql, kl, vl, 1, 0);

    // 4. flash attention (tensor cores) -> bf16 hi/lo [n,s,e]
    attn_mma_kernel<<<dim3(SQ / 128, HH, NB), 256, ATT_SMEM>>>(
        qh, ql, kh, kl, vh, vl, m8, aoh, aol);

    // 5. out projection -> f32 out
    gemm_mma_kernel<<<dim3(EE / 128, NB * SQ / 128, 1), 256, GEMM_SMEM>>>(
        aoh, aol, wth, wtl, bo, bo, bo, out,
        nullptr, nullptr, nullptr, nullptr, nullptr, nullptr, 0, 3);
}

// round 6
// speedup vs baseline: 4.6277x; 1.1191x over previous
#include <cuda_runtime.h>
#include <cuda_bf16.h>
#include <cstdint>

// Problem dims
#define NB   8
#define SQ   1024
#define EE   1024
#define HH   16
#define DK   64

// -------------------- scratch (static device arrays; no allocation) -----------
__device__ unsigned char g_mask8[NB * SQ * SQ];
__device__ int g_mask_fmt;

__device__ __nv_bfloat16 g_xh[NB * SQ * EE];
__device__ __nv_bfloat16 g_xl[NB * SQ * EE];
__device__ __nv_bfloat16 g_wth[4 * EE * EE];     // W^T hi/lo, [n][k], 4 mats
__device__ __nv_bfloat16 g_wtl[4 * EE * EE];
__device__ __nv_bfloat16 g_qh[NB * HH * SQ * DK];   // [n,h,s,d] bf16 hi/lo
__device__ __nv_bfloat16 g_ql[NB * HH * SQ * DK];
__device__ __nv_bfloat16 g_kh[NB * HH * SQ * DK];
__device__ __nv_bfloat16 g_kl[NB * HH * SQ * DK];
__device__ __nv_bfloat16 g_vh[NB * HH * SQ * DK];
__device__ __nv_bfloat16 g_vl[NB * HH * SQ * DK];
__device__ __nv_bfloat16 g_aoh[NB * SQ * EE];    // attn-out hi/lo, [n,s,e]
__device__ __nv_bfloat16 g_aol[NB * SQ * EE];

// -------------------- helpers --------------------------------------------------
__device__ __forceinline__ uint32_t smem_u32(const void* p) {
    uint32_t a;
    asm("{ .reg .u64 t; cvta.to.shared.u64 t, %1; cvt.u32.u64 %0, t; }" : "=r"(a) : "l"(p));
    return a;
}
__device__ __forceinline__ void cp_async16(uint32_t dst, const void* src) {
    asm volatile("cp.async.cg.shared.global [%0], [%1], 16;" :: "r"(dst), "l"(src));
}
#define CP_COMMIT() asm volatile("cp.async.commit_group;" ::: "memory")
#define CP_WAIT1()  asm volatile("cp.async.wait_group 1;" ::: "memory")

__device__ __forceinline__ void ldsm4(uint32_t* r, uint32_t addr) {
    asm volatile("ldmatrix.sync.aligned.m8n8.x4.shared.b16 {%0,%1,%2,%3}, [%4];"
        : "=r"(r[0]), "=r"(r[1]), "=r"(r[2]), "=r"(r[3]) : "r"(addr));
}
__device__ __forceinline__ void ldsm4t(uint32_t* r, uint32_t addr) {
    asm volatile("ldmatrix.sync.aligned.m8n8.x4.trans.shared.b16 {%0,%1,%2,%3}, [%4];"
        : "=r"(r[0]), "=r"(r[1]), "=r"(r[2]), "=r"(r[3]) : "r"(addr));
}
__device__ __forceinline__ void mma_bf16(float* c, const uint32_t* a, uint32_t b0, uint32_t b1) {
    asm volatile(
        "mma.sync.aligned.m16n8k16.row.col.f32.bf16.bf16.f32 "
        "{%0,%1,%2,%3}, {%4,%5,%6,%7}, {%8,%9}, {%0,%1,%2,%3};"
        : "+f"(c[0]), "+f"(c[1]), "+f"(c[2]), "+f"(c[3])
        : "r"(a[0]), "r"(a[1]), "r"(a[2]), "r"(a[3]), "r"(b0), "r"(b1));
}
__device__ __forceinline__ uint32_t pack_bf16(float x, float y) {
    __nv_bfloat162 t = __floats2bfloat162_rn(x, y);
    return *(uint32_t*)&t;
}

// -------------------- mask dtype detection + conversion ----------------------
__global__ void detect_mask_kernel(const unsigned int* __restrict__ m) {
    __shared__ int s01, sf;
    if (threadIdx.x == 0) { s01 = 1; sf = 1; }
    __syncthreads();
    unsigned int v = m[threadIdx.x];
    if (v > 1u) s01 = 0;
    if (v != 0u && v != 0x3F800000u) sf = 0;
    __syncthreads();
    if (threadIdx.x == 0) g_mask_fmt = s01 ? 0 : (sf ? 1 : 2);
}

__global__ void convert_mask_kernel(const void* __restrict__ m, int n) {
    int i = blockIdx.x * blockDim.x + threadIdx.x;
    if (i >= n) return;
    int fmt = g_mask_fmt;
    unsigned char v;
    if (fmt == 0)      v = (((const int*)m)[i]   != 0)    ? 1 : 0;
    else if (fmt == 1) v = (((const float*)m)[i] != 0.0f) ? 1 : 0;
    else               v = (((const unsigned char*)m)[i] != 0) ? 1 : 0;
    g_mask8[i] = v;
}

// -------------------- fp32 -> bf16 hi/lo split (x only) ------------------------
__global__ void split_kernel(const float* __restrict__ in,
                             __nv_bfloat16* __restrict__ oh,
                             __nv_bfloat16* __restrict__ ol) {
    int i = blockIdx.x * blockDim.x + threadIdx.x;
    float4 v = ((const float4*)in)[i];
    __nv_bfloat16 h0 = __float2bfloat16(v.x), h1 = __float2bfloat16(v.y);
    __nv_bfloat16 h2 = __float2bfloat16(v.z), h3 = __float2bfloat16(v.w);
    float l0 = v.x - __bfloat162float(h0), l1 = v.y - __bfloat162float(h1);
    float l2 = v.z - __bfloat162float(h2), l3 = v.w - __bfloat162float(h3);
    __nv_bfloat162* oh2 = (__nv_bfloat162*)oh;
    __nv_bfloat162* ol2 = (__nv_bfloat162*)ol;
    oh2[i * 2]     = __nv_bfloat162(h0, h1);
    oh2[i * 2 + 1] = __nv_bfloat162(h2, h3);
    ol2[i * 2]     = __floats2bfloat162_rn(l0, l1);
    ol2[i * 2 + 1] = __floats2bfloat162_rn(l2, l3);
}

// -------------------- W -> W^T hi/lo bf16 --------------------------------------
__global__ void convert_wt_kernel(const float* __restrict__ W0, const float* __restrict__ W1,
                                  const float* __restrict__ W2, const float* __restrict__ W3,
                                  __nv_bfloat16* __restrict__ wth, __nv_bfloat16* __restrict__ wtl) {
    const float* W = (blockIdx.z == 0) ? W0 : (blockIdx.z == 1) ? W1 : (blockIdx.z == 2) ? W2 : W3;
    __shared__ float t[32][33];
    int tx = threadIdx.x, ty = threadIdx.y;
    int k0 = blockIdx.y * 32, n0 = blockIdx.x * 32;
#pragma unroll
    for (int j = 0; j < 4; j++)
        t[ty + 8 * j][tx] = W[(size_t)(k0 + ty + 8 * j) * EE + n0 + tx];
    __syncthreads();
    size_t off = (size_t)blockIdx.z << 20;
#pragma unroll
    for (int j = 0; j < 4; j++) {
        float f = t[tx][ty + 8 * j];
        __nv_bfloat16 h = __float2bfloat16(f);
        size_t o = off + (size_t)(n0 + ty + 8 * j) * EE + k0 + tx;
        wth[o] = h;
        wtl[o] = __float2bfloat16(f - __bfloat162float(h));
    }
}

// -------------------- mma.sync split-bf16 GEMM (KC=32, 2 CTAs/SM) --------------
#define TSZ        8192           // 128 rows x 64B (32 bf16)
#define STAGE_B    (4 * TSZ)      // 32KB
#define GEMM_SMEM  (3 * STAGE_B)  // 96KB
#define NKC        32

// 64B-row swizzle: chunk c (16B units, 0..3) -> c ^ ((r>>1)&3)
__device__ __forceinline__ void load_stage(
    uint32_t sb, const __nv_bfloat16* ah, const __nv_bfloat16* al,
    const __nv_bfloat16* bh, const __nv_bfloat16* bl, int kc, int tid)
{
    const __nv_bfloat16* bases[4] = {ah, al, bh, bl};
#pragma unroll
    for (int t4 = 0; t4 < 4; t4++) {
        const __nv_bfloat16* base = bases[t4] + kc * 32;
        uint32_t dtile = sb + t4 * TSZ;
#pragma unroll
        for (int p = 0; p < 2; p++) {
            int idx = p * 256 + tid;
            int r = idx >> 2, c = idx & 3;
            cp_async16(dtile + r * 64 + ((c ^ ((r >> 1) & 3)) << 4),
                       base + (size_t)r * EE + c * 8);
        }
    }
}

__global__ void __launch_bounds__(256, 2) gemm_mma_kernel(
    const __nv_bfloat16* __restrict__ Ah, const __nv_bfloat16* __restrict__ Al,
    const __nv_bfloat16* __restrict__ Wh, const __nv_bfloat16* __restrict__ Wl,
    const float* __restrict__ b0, const float* __restrict__ b1, const float* __restrict__ b2,
    float* fo,
    __nv_bfloat16* oh0, __nv_bfloat16* oh1, __nv_bfloat16* oh2,
    __nv_bfloat16* ol0, __nv_bfloat16* ol1, __nv_bfloat16* ol2,
    int headmajor, int wbase)
{
    extern __shared__ char smem[];
    const uint32_t sbase = smem_u32(smem);
    const int tid = threadIdx.x;
    const int z = blockIdx.z;
    const float* bias = (z == 0) ? b0 : (z == 1) ? b1 : b2;
    __nv_bfloat16* oh = (z == 0) ? oh0 : (z == 1) ? oh1 : oh2;
    __nv_bfloat16* ol = (z == 0) ? ol0 : (z == 1) ? ol1 : ol2;
    const size_t woff = ((size_t)(wbase + z)) << 20;

    const int mBase = blockIdx.y * 128;
    const int nBase = blockIdx.x * 128;
    const __nv_bfloat16* ah = Ah + (size_t)mBase * EE;
    const __nv_bfloat16* al = Al + (size_t)mBase * EE;
    const __nv_bfloat16* bh = Wh + woff + (size_t)nBase * EE;
    const __nv_bfloat16* bl = Wl + woff + (size_t)nBase * EE;

    load_stage(sbase + 0 * STAGE_B, ah, al, bh, bl, 0, tid);
    CP_COMMIT();
    load_stage(sbase + 1 * STAGE_B, ah, al, bh, bl, 1, tid);
    CP_COMMIT();

    const int lane = tid & 31;
    const int wm = (tid >> 5) & 1;
    const int wn = tid >> 6;
    const int l15 = lane & 15, l16 = lane >> 4;

    float c[4][4][4];
#pragma unroll
    for (int i = 0; i < 4; i++)
#pragma unroll
        for (int j = 0; j < 4; j++)
#pragma unroll
            for (int q = 0; q < 4; q++) c[i][j][q] = 0.0f;

    for (int kc = 0; kc < NKC; kc++) {
        CP_WAIT1();
        __syncthreads();
        if (kc + 2 < NKC)
            load_stage(sbase + ((kc + 2) % 3) * STAGE_B, ah, al, bh, bl, kc + 2, tid);
        CP_COMMIT();

        const uint32_t sb = sbase + (kc % 3) * STAGE_B;
#pragma unroll
        for (int ko = 0; ko < 2; ko++) {
            uint32_t a[4][4], bh0[4], bh1[4], bl0[4], bl1[4];
            const int ch = ko * 2 + l16;
#pragma unroll
            for (int i = 0; i < 4; i++) {
                int r = wm * 64 + i * 16 + l15;
                ldsm4(a[i], sb + r * 64 + ((ch ^ ((r >> 1) & 3)) << 4));
            }
            {
                int r0 = wn * 32 + l15;
                ldsm4(bh0, sb + 2 * TSZ + r0 * 64 + ((ch ^ ((r0 >> 1) & 3)) << 4));
                int r1 = wn * 32 + 16 + l15;
                ldsm4(bh1, sb + 2 * TSZ + r1 * 64 + ((ch ^ ((r1 >> 1) & 3)) << 4));
                ldsm4(bl0, sb + 3 * TSZ + r0 * 64 + ((ch ^ ((r0 >> 1) & 3)) << 4));
                ldsm4(bl1, sb + 3 * TSZ + r1 * 64 + ((ch ^ ((r1 >> 1) & 3)) << 4));
            }
#pragma unroll
            for (int i = 0; i < 4; i++) {
                mma_bf16(c[i][0], a[i], bh0[0], bh0[2]);
                mma_bf16(c[i][1], a[i], bh0[1], bh0[3]);
                mma_bf16(c[i][2], a[i], bh1[0], bh1[2]);
                mma_bf16(c[i][3], a[i], bh1[1], bh1[3]);
                mma_bf16(c[i][0], a[i], bl0[0], bl0[2]);
                mma_bf16(c[i][1], a[i], bl0[1], bl0[3]);
                mma_bf16(c[i][2], a[i], bl1[0], bl1[2]);
                mma_bf16(c[i][3], a[i], bl1[1], bl1[3]);
            }
#pragma unroll
            for (int i = 0; i < 4; i++) {
                int r = wm * 64 + i * 16 + l15;
                ldsm4(a[i], sb + TSZ + r * 64 + ((ch ^ ((r >> 1) & 3)) << 4));
            }
#pragma unroll
            for (int i = 0; i < 4; i++) {
                mma_bf16(c[i][0], a[i], bh0[0], bh0[2]);
                mma_bf16(c[i][1], a[i], bh0[1], bh0[3]);
                mma_bf16(c[i][2], a[i], bh1[0], bh1[2]);
                mma_bf16(c[i][3], a[i], bh1[1], bh1[3]);
            }
        }
    }

    const int lr = lane >> 2, lc = lane & 3;
#pragma unroll
    for (int i = 0; i < 4; i++) {
#pragma unroll
        for (int half = 0; half < 2; half++) {
            const int R = mBase + wm * 64 + i * 16 + half * 8 + lr;
#pragma unroll
            for (int j = 0; j < 4; j++) {
                const int C0 = nBase + wn * 32 + j * 8 + lc * 2;
                float2 bv = *(const float2*)(bias + C0);
                float vx = c[i][j][half * 2 + 0] + bv.x;
                float vy = c[i][j][half * 2 + 1] + bv.y;
                if (headmajor) {
                    const int nidx = R >> 10, sidx = R & 1023;
                    const int head = C0 >> 6, dd = C0 & 63;
                    size_t off = (((size_t)(nidx * HH + head) * SQ + sidx) << 6) + dd;
                    __nv_bfloat16 h0 = __float2bfloat16(vx), h1 = __float2bfloat16(vy);
                    __nv_bfloat162 hp(h0, h1);
                    __nv_bfloat162 lp = __floats2bfloat162_rn(vx - __bfloat162float(h0),
                                                              vy - __bfloat162float(h1));
                    *(__nv_bfloat162*)(oh + off) = hp;
                    *(__nv_bfloat162*)(ol + off) = lp;
                } else {
                    *(float2*)(fo + (size_t)R * EE + C0) = make_float2(vx, vy);
                }
            }
        }
    }
}

// -------------------- flash attention on mma.sync (2-stage, 2 CTAs/SM) ---------
// CTA: 128 q-rows x 1 head. 8 warps x 16 rows. kv tiles of 64.
// smem: Q hi/lo 32KB + 2 stages x (Kh,Kl,Vh,Vl 8KB each + mask 8KB) = 112KB.
#define AQ_L     16384
#define ASTAGE   40960
#define AST(s)   (32768 + (s) * ASTAGE)
#define A_KL     8192
#define A_VH     16384
#define A_VL     24576
#define A_M      32768
#define ATT_SMEM (32768 + 2 * ASTAGE)

__device__ __forceinline__ void att_load_stage(
    uint32_t sb, int st, const __nv_bfloat16* kh, const __nv_bfloat16* kl,
    const __nv_bfloat16* vh, const __nv_bfloat16* vl,
    const unsigned char* mbase, int kt, int tid)
{
    const __nv_bfloat16* bases[4] = {kh, kl, vh, vl};
#pragma unroll
    for (int t4 = 0; t4 < 4; t4++) {
        const __nv_bfloat16* base = bases[t4] + (size_t)kt * 64 * DK;
        uint32_t dtile = sb + AST(st) + t4 * 8192;
#pragma unroll
        for (int p = 0; p < 2; p++) {
            int idx = p * 256 + tid;
            int r = idx >> 3, c = idx & 7;
            cp_async16(dtile + r * 128 + ((c ^ (r & 7)) << 4), base + r * 64 + c * 8);
        }
    }
    // mask tile: 128 rows x 64 u8
#pragma unroll
    for (int p = 0; p < 2; p++) {
        int idx = p * 256 + tid;
        int r = idx >> 2, c = idx & 3;
        cp_async16(sb + AST(st) + A_M + r * 64 + c * 16,
                   mbase + (size_t)r * SQ + kt * 64 + c * 16);
    }
}

__global__ void __launch_bounds__(256, 2) attn_mma_kernel(
    const __nv_bfloat16* __restrict__ Qh, const __nv_bfloat16* __restrict__ Ql,
    const __nv_bfloat16* __restrict__ Kh, const __nv_bfloat16* __restrict__ Kl,
    const __nv_bfloat16* __restrict__ Vh, const __nv_bfloat16* __restrict__ Vl,
    const unsigned char* __restrict__ mask8,
    __nv_bfloat16* __restrict__ Oh, __nv_bfloat16* __restrict__ Ol)
{
    extern __shared__ char smem[];
    const uint32_t sb = smem_u32(smem);
    const int tid = threadIdx.x;
    const int qt = blockIdx.x, h = blockIdx.y, n = blockIdx.z;

    const size_t hoff = (size_t)(n * HH + h) * SQ * DK;
    const __nv_bfloat16* qh = Qh + hoff + (size_t)qt * 128 * DK;
    const __nv_bfloat16* ql = Ql + hoff + (size_t)qt * 128 * DK;
    const __nv_bfloat16* kh = Kh + hoff;
    const __nv_bfloat16* kl = Kl + hoff;
    const __nv_bfloat16* vh = Vh + hoff;
    const __nv_bfloat16* vl = Vl + hoff;
    const unsigned char* mbase = mask8 + ((size_t)n * SQ + qt * 128) * SQ;

    // Q hi/lo load (group 0, together with stage 0)
#pragma unroll
    for (int p = 0; p < 4; p++) {
        int idx = p * 256 + tid;
        int r = idx >> 3, c = idx & 7;
        uint32_t sw = r * 128 + ((c ^ (r & 7)) << 4);
        cp_async16(sb + sw, qh + r * 64 + c * 8);
        cp_async16(sb + AQ_L + sw, ql + r * 64 + c * 8);
    }
    att_load_stage(sb, 0, kh, kl, vh, vl, mbase, 0, tid);
    CP_COMMIT();
    att_load_stage(sb, 1, kh, kl, vh, vl, mbase, 1, tid);
    CP_COMMIT();

    const int w = tid >> 5, lane = tid & 31;
    const int l15 = lane & 15, l16 = lane >> 4;
    const int lr = lane >> 2, lc = lane & 3;
    const int row0 = w * 16 + lr;             // local q row for c[..][0,1]
    const int qg0 = qt * 128 + row0;
    const int qg1 = qg0 + 8;

    float o[8][4];
#pragma unroll
    for (int i = 0; i < 8; i++)
#pragma unroll
        for (int j = 0; j < 4; j++) o[i][j] = 0.0f;
    float m0 = -1e30f, m1 = -1e30f, l0 = 0.0f, l1 = 0.0f;

    for (int kt = 0; kt < 16; kt++) {
        CP_WAIT1();
        __syncthreads();

        const uint32_t stg = sb + AST(kt & 1);
        const char* mp = smem + AST(kt & 1) + A_M;

        // ---- S = Q K^T (split) ----
        float s[8][4];
#pragma unroll
        for (int i = 0; i < 8; i++)
#pragma unroll
            for (int j = 0; j < 4; j++) s[i][j] = 0.0f;

#pragma unroll
        for (int ko = 0; ko < 4; ko++) {
            const int ch = 2 * ko + l16;
            uint32_t aqh[4], aql[4];
            {
                int r = w * 16 + l15;
                uint32_t sw = r * 128 + ((ch ^ (r & 7)) << 4);
                ldsm4(aqh, sb + sw);
                ldsm4(aql, sb + AQ_L + sw);
            }
#pragma unroll
            for (int nt2 = 0; nt2 < 4; nt2++) {
                int rk = nt2 * 16 + l15;
                uint32_t sw = rk * 128 + ((ch ^ (rk & 7)) << 4);
                uint32_t kb[4], klb[4];
                ldsm4(kb,  stg + sw);
                ldsm4(klb, stg + A_KL + sw);
                mma_bf16(s[2 * nt2],     aqh, kb[0], kb[2]);
                mma_bf16(s[2 * nt2 + 1], aqh, kb[1], kb[3]);
                mma_bf16(s[2 * nt2],     aql, kb[0], kb[2]);
                mma_bf16(s[2 * nt2 + 1], aql, kb[1], kb[3]);
                mma_bf16(s[2 * nt2],     aqh, klb[0], klb[2]);
                mma_bf16(s[2 * nt2 + 1], aqh, klb[1], klb[3]);
            }
        }

        // ---- scale + mask (from smem) ----
#pragma unroll
        for (int nt = 0; nt < 8; nt++) {
            unsigned short k0 = *(const unsigned short*)(mp + row0 * 64 + nt * 8 + 2 * lc);
            unsigned short k1 = *(const unsigned short*)(mp + (row0 + 8) * 64 + nt * 8 + 2 * lc);
            s[nt][0] = (k0 & 0x00FF) ? -1e9f : s[nt][0] * 0.125f;
            s[nt][1] = (k0 & 0xFF00) ? -1e9f : s[nt][1] * 0.125f;
            s[nt][2] = (k1 & 0x00FF) ? -1e9f : s[nt][2] * 0.125f;
            s[nt][3] = (k1 & 0xFF00) ? -1e9f : s[nt][3] * 0.125f;
        }

        // ---- online softmax ----
        float vx0 = -1e30f, vx1 = -1e30f;
#pragma unroll
        for (int nt = 0; nt < 8; nt++) {
            vx0 = fmaxf(vx0, fmaxf(s[nt][0], s[nt][1]));
            vx1 = fmaxf(vx1, fmaxf(s[nt][2], s[nt][3]));
        }
        vx0 = fmaxf(vx0, __shfl_xor_sync(0xffffffffu, vx0, 1));
        vx0 = fmaxf(vx0, __shfl_xor_sync(0xffffffffu, vx0, 2));
        vx1 = fmaxf(vx1, __shfl_xor_sync(0xffffffffu, vx1, 1));
        vx1 = fmaxf(vx1, __shfl_xor_sync(0xffffffffu, vx1, 2));

        float mn0 = fmaxf(m0, vx0), mn1 = fmaxf(m1, vx1);
        float a0 = __expf(m0 - mn0), a1 = __expf(m1 - mn1);
        m0 = mn0; m1 = mn1;
        float sum0 = 0.0f, sum1 = 0.0f;
#pragma unroll
        for (int nt = 0; nt < 8; nt++) {
            s[nt][0] = __expf(s[nt][0] - mn0);
            s[nt][1] = __expf(s[nt][1] - mn0);
            s[nt][2] = __expf(s[nt][2] - mn1);
            s[nt][3] = __expf(s[nt][3] - mn1);
            sum0 += s[nt][0] + s[nt][1];
            sum1 += s[nt][2] + s[nt][3];
        }
        sum0 += __shfl_xor_sync(0xffffffffu, sum0, 1);
        sum0 += __shfl_xor_sync(0xffffffffu, sum0, 2);
        sum1 += __shfl_xor_sync(0xffffffffu, sum1, 1);
        sum1 += __shfl_xor_sync(0xffffffffu, sum1, 2);
        l0 = l0 * a0 + sum0;
        l1 = l1 * a1 + sum1;
#pragma unroll
        for (int nt = 0; nt < 8; nt++) {
            o[nt][0] *= a0; o[nt][1] *= a0;
            o[nt][2] *= a1; o[nt][3] *= a1;
        }

        // ---- O += P V (split) ----
#pragma unroll
        for (int t = 0; t < 4; t++) {
            uint32_t ph[4], pl[4];
            {
                float p0 = s[2 * t][0],     p1 = s[2 * t][1];
                float p2 = s[2 * t][2],     p3 = s[2 * t][3];
                float p4 = s[2 * t + 1][0], p5 = s[2 * t + 1][1];
                float p6 = s[2 * t + 1][2], p7 = s[2 * t + 1][3];
                __nv_bfloat16 h0 = __float2bfloat16(p0), h1 = __float2bfloat16(p1);
                __nv_bfloat16 h2 = __float2bfloat16(p2), h3 = __float2bfloat16(p3);
                __nv_bfloat16 h4 = __float2bfloat16(p4), h5 = __float2bfloat16(p5);
                __nv_bfloat16 h6 = __float2bfloat16(p6), h7 = __float2bfloat16(p7);
                __nv_bfloat162 t0(h0, h1), t1(h2, h3), t2(h4, h5), t3(h6, h7);
                ph[0] = *(uint32_t*)&t0; ph[1] = *(uint32_t*)&t1;
                ph[2] = *(uint32_t*)&t2; ph[3] = *(uint32_t*)&t3;
                pl[0] = pack_bf16(p0 - __bfloat162float(h0), p1 - __bfloat162float(h1));
                pl[1] = pack_bf16(p2 - __bfloat162float(h2), p3 - __bfloat162float(h3));
                pl[2] = pack_bf16(p4 - __bfloat162float(h4), p5 - __bfloat162float(h5));
                pl[3] = pack_bf16(p6 - __bfloat162float(h6), p7 - __bfloat162float(h7));
            }
#pragma unroll
            for (int dt2 = 0; dt2 < 4; dt2++) {
                int rv = t * 16 + l15;
                int chd = 2 * dt2 + l16;
                uint32_t sw = rv * 128 + ((chd ^ (rv & 7)) << 4);
                uint32_t vbh[4], vbl[4];
                ldsm4t(vbh, stg + A_VH + sw);
                ldsm4t(vbl, stg + A_VL + sw);
                mma_bf16(o[2 * dt2],     ph, vbh[0], vbh[1]);
                mma_bf16(o[2 * dt2 + 1], ph, vbh[2], vbh[3]);
                mma_bf16(o[2 * dt2],     pl, vbh[0], vbh[1]);
                mma_bf16(o[2 * dt2 + 1], pl, vbh[2], vbh[3]);
                mma_bf16(o[2 * dt2],     ph, vbl[0], vbl[1]);
                mma_bf16(o[2 * dt2 + 1], ph, vbl[2], vbl[3]);
            }
        }

        __syncthreads();   // all warps done with buffer (kt&1) before reload
        if (kt + 2 < 16)
            att_load_stage(sb, kt & 1, kh, kl, vh, vl, mbase, kt + 2, tid);
        CP_COMMIT();
    }

    // ---- epilogue: normalize, split to bf16 hi/lo, store [n,s,e] ----
    const float inv0 = 1.0f / l0, inv1 = 1.0f / l1;
    const size_t base0 = ((size_t)n * SQ + qg0) * EE + h * DK + 2 * lc;
    const size_t base1 = ((size_t)n * SQ + qg1) * EE + h * DK + 2 * lc;
#pragma unroll
    for (int nt = 0; nt < 8; nt++) {
        float vx = o[nt][0] * inv0, vy = o[nt][1] * inv0;
        __nv_bfloat16 h0 = __float2bfloat16(vx), h1 = __float2bfloat16(vy);
        __nv_bfloat162 hp(h0, h1);
        __nv_bfloat162 lp = __floats2bfloat162_rn(vx - __bfloat162float(h0),
                                                  vy - __bfloat162float(h1));
        *(__nv_bfloat162*)(Oh + base0 + nt * 8) = hp;
        *(__nv_bfloat162*)(Ol + base0 + nt * 8) = lp;

        vx = o[nt][2] * inv1; vy = o[nt][3] * inv1;
        h0 = __float2bfloat16(vx); h1 = __float2bfloat16(vy);
        __nv_bfloat162 hp1(h0, h1);
        __nv_bfloat162 lp1 = __floats2bfloat162_rn(vx - __bfloat162float(h0),
                                                   vy - __bfloat162float(h1));
        *(__nv_bfloat162*)(Oh + base1 + nt * 8) = hp1;
        *(__nv_bfloat162*)(Ol + base1 + nt * 8) = lp1;
    }
}

// -------------------- launch ---------------------------------------------------
extern "C" void kernel_launch(void* const* d_in, const int* in_sizes, int n_in,
                              void* d_out, int out_size)
{
    const float* x    = (const float*)d_in[0];
    const void*  mask = d_in[1];
    const float* Wq   = (const float*)d_in[2];
    const float* bq   = (const float*)d_in[3];
    const float* Wk   = (const float*)d_in[4];
    const float* bk   = (const float*)d_in[5];
    const float* Wv   = (const float*)d_in[6];
    const float* bv   = (const float*)d_in[7];
    const float* Wo   = (const float*)d_in[8];
    const float* bo   = (const float*)d_in[9];
    float* out = (float*)d_out;

    unsigned char* m8;
    cudaGetSymbolAddress((void**)&m8, g_mask8);
    __nv_bfloat16 *xh, *xl, *wth, *wtl, *aoh, *aol;
    __nv_bfloat16 *qh, *ql, *kh, *kl, *vh, *vl;
    cudaGetSymbolAddress((void**)&xh,  g_xh);
    cudaGetSymbolAddress((void**)&xl,  g_xl);
    cudaGetSymbolAddress((void**)&wth, g_wth);
    cudaGetSymbolAddress((void**)&wtl, g_wtl);
    cudaGetSymbolAddress((void**)&aoh, g_aoh);
    cudaGetSymbolAddress((void**)&aol, g_aol);
    cudaGetSymbolAddress((void**)&qh,  g_qh);
    cudaGetSymbolAddress((void**)&ql,  g_ql);
    cudaGetSymbolAddress((void**)&kh,  g_kh);
    cudaGetSymbolAddress((void**)&kl,  g_kl);
    cudaGetSymbolAddress((void**)&vh,  g_vh);
    cudaGetSymbolAddress((void**)&vl,  g_vl);

    cudaFuncSetAttribute(gemm_mma_kernel,
                         cudaFuncAttributeMaxDynamicSharedMemorySize, GEMM_SMEM);
    cudaFuncSetAttribute(attn_mma_kernel,
                         cudaFuncAttributeMaxDynamicSharedMemorySize, ATT_SMEM);

    // 1. mask detect + convert
    detect_mask_kernel<<<1, 256>>>((const unsigned int*)mask);
    int nmask = NB * SQ * SQ;
    convert_mask_kernel<<<(nmask + 255) / 256, 256>>>(mask, nmask);

    // 2. split x, build W^T hi/lo
    int nelem4 = NB * SQ * EE / 4;
    split_kernel<<<nelem4 / 256, 256>>>(x, xh, xl);
    convert_wt_kernel<<<dim3(32, 32, 4), dim3(32, 8)>>>(Wq, Wk, Wv, Wo, wth, wtl);

    // 3. QKV projections -> bf16 hi/lo head-major
    gemm_mma_kernel<<<dim3(EE / 128, NB * SQ / 128, 3), 256, GEMM_SMEM>>>(
        xh, xl, wth, wtl, bq, bk, bv, nullptr,
        qh, kh, vh, ql, kl, vl, 1, 0);

    // 4. flash attention (tensor cores) -> bf16 hi/lo [n,s,e]
    attn_mma_kernel<<<dim3(SQ / 128, HH, NB), 256, ATT_SMEM>>>(
        qh, ql, kh, kl, vh, vl, m8, aoh, aol);

    // 5. out projection -> f32 out
    gemm_mma_kernel<<<dim3(EE / 128, NB * SQ / 128, 1), 256, GEMM_SMEM>>>(
        aoh, aol, wth, wtl, bo, bo, bo, out,
        nullptr, nullptr, nullptr, nullptr, nullptr, nullptr, 0, 3);
}

// round 9
// speedup vs baseline: 5.4233x; 1.1719x over previous
#include <cuda_runtime.h>
#include <cuda_bf16.h>
#include <cuda_fp16.h>
#include <cstdint>

// Problem dims
#define NB   8
#define SQ   1024
#define EE   1024
#define HH   16
#define DK   64

// -------------------- scratch (static device arrays; no allocation) -----------
__device__ unsigned long long g_maskb[NB * SQ * 16];   // bit-packed, [n][kt][qrow]
__device__ int g_mask_fmt;

__device__ __nv_bfloat16 g_xh[NB * SQ * EE];
__device__ __nv_bfloat16 g_xl[NB * SQ * EE];
__device__ __nv_bfloat16 g_wth[4 * EE * EE];     // W^T hi/lo, [n][k], 4 mats
__device__ __nv_bfloat16 g_wtl[4 * EE * EE];
__device__ __half g_qf[NB * HH * SQ * DK];       // [n,h,s,d] fp16
__device__ __half g_kf[NB * HH * SQ * DK];
__device__ __half g_vf[NB * HH * SQ * DK];
__device__ __nv_bfloat16 g_aoh[NB * SQ * EE];    // attn-out hi/lo, [n,s,e]
__device__ __nv_bfloat16 g_aol[NB * SQ * EE];

// -------------------- helpers --------------------------------------------------
__device__ __forceinline__ uint32_t smem_u32(const void* p) {
    uint32_t a;
    asm("{ .reg .u64 t; cvta.to.shared.u64 t, %1; cvt.u32.u64 %0, t; }" : "=r"(a) : "l"(p));
    return a;
}
__device__ __forceinline__ void cp_async16(uint32_t dst, const void* src) {
    asm volatile("cp.async.cg.shared.global [%0], [%1], 16;" :: "r"(dst), "l"(src));
}
#define CP_COMMIT() asm volatile("cp.async.commit_group;" ::: "memory")
#define CP_WAIT1()  asm volatile("cp.async.wait_group 1;" ::: "memory")
#define CP_WAIT0()  asm volatile("cp.async.wait_group 0;" ::: "memory")

__device__ __forceinline__ void ldsm4(uint32_t* r, uint32_t addr) {
    asm volatile("ldmatrix.sync.aligned.m8n8.x4.shared.b16 {%0,%1,%2,%3}, [%4];"
        : "=r"(r[0]), "=r"(r[1]), "=r"(r[2]), "=r"(r[3]) : "r"(addr));
}
__device__ __forceinline__ void ldsm4t(uint32_t* r, uint32_t addr) {
    asm volatile("ldmatrix.sync.aligned.m8n8.x4.trans.shared.b16 {%0,%1,%2,%3}, [%4];"
        : "=r"(r[0]), "=r"(r[1]), "=r"(r[2]), "=r"(r[3]) : "r"(addr));
}
__device__ __forceinline__ void mma_bf16(float* c, const uint32_t* a, uint32_t b0, uint32_t b1) {
    asm volatile(
        "mma.sync.aligned.m16n8k16.row.col.f32.bf16.bf16.f32 "
        "{%0,%1,%2,%3}, {%4,%5,%6,%7}, {%8,%9}, {%0,%1,%2,%3};"
        : "+f"(c[0]), "+f"(c[1]), "+f"(c[2]), "+f"(c[3])
        : "r"(a[0]), "r"(a[1]), "r"(a[2]), "r"(a[3]), "r"(b0), "r"(b1));
}
__device__ __forceinline__ void mma_f16(float* c, const uint32_t* a, uint32_t b0, uint32_t b1) {
    asm volatile(
        "mma.sync.aligned.m16n8k16.row.col.f32.f16.f16.f32 "
        "{%0,%1,%2,%3}, {%4,%5,%6,%7}, {%8,%9}, {%0,%1,%2,%3};"
        : "+f"(c[0]), "+f"(c[1]), "+f"(c[2]), "+f"(c[3])
        : "r"(a[0]), "r"(a[1]), "r"(a[2]), "r"(a[3]), "r"(b0), "r"(b1));
}
__device__ __forceinline__ uint32_t pack_f16(float x, float y) {
    __half2 t = __floats2half2_rn(x, y);
    return *(uint32_t*)&t;
}

// -------------------- mask dtype detection + bit packing ----------------------
__global__ void detect_mask_kernel(const unsigned int* __restrict__ m) {
    __shared__ int s01, sf;
    if (threadIdx.x == 0) { s01 = 1; sf = 1; }
    __syncthreads();
    unsigned int v = m[threadIdx.x];
    if (v > 1u) s01 = 0;
    if (v != 0u && v != 0x3F800000u) sf = 0;
    __syncthreads();
    if (threadIdx.x == 0) g_mask_fmt = s01 ? 0 : (sf ? 1 : 2);
}

// one warp -> one u64 word covering 64 mask cols; out layout [n][kt][qrow]
__global__ void mask_bits_kernel(const void* __restrict__ m,
                                 unsigned long long* __restrict__ out) {
    int gw = (blockIdx.x * blockDim.x + threadIdx.x) >> 5;
    int lane = threadIdx.x & 31;
    int n = gw >> 14;
    int rem = gw & 16383;
    int qrow = rem >> 4;
    int kt = rem & 15;
    size_t base = ((size_t)(n * SQ + qrow)) * SQ + kt * 64;
    int fmt = g_mask_fmt;
    unsigned a, b;
    if (fmt == 2) {
        const unsigned char* p = (const unsigned char*)m + base;
        a = (p[lane] != 0); b = (p[lane + 32] != 0);
    } else {
        const unsigned* p = (const unsigned*)m + base;
        unsigned va = p[lane], vb = p[lane + 32];
        if (fmt == 1) { va &= 0x7fffffffu; vb &= 0x7fffffffu; }
        a = (va != 0); b = (vb != 0);
    }
    unsigned lo = __ballot_sync(0xffffffffu, a);
    unsigned hi = __ballot_sync(0xffffffffu, b);
    if (lane == 0)
        out[((size_t)(n * 16 + kt)) * SQ + qrow] =
            ((unsigned long long)hi << 32) | lo;
}

// -------------------- fp32 -> bf16 hi/lo split (x only) ------------------------
__global__ void split_kernel(const float* __restrict__ in,
                             __nv_bfloat16* __restrict__ oh,
                             __nv_bfloat16* __restrict__ ol) {
    int i = blockIdx.x * blockDim.x + threadIdx.x;
    float4 v = ((const float4*)in)[i];
    __nv_bfloat16 h0 = __float2bfloat16(v.x), h1 = __float2bfloat16(v.y);
    __nv_bfloat16 h2 = __float2bfloat16(v.z), h3 = __float2bfloat16(v.w);
    float l0 = v.x - __bfloat162float(h0), l1 = v.y - __bfloat162float(h1);
    float l2 = v.z - __bfloat162float(h2), l3 = v.w - __bfloat162float(h3);
    __nv_bfloat162* oh2 = (__nv_bfloat162*)oh;
    __nv_bfloat162* ol2 = (__nv_bfloat162*)ol;
    oh2[i * 2]     = __nv_bfloat162(h0, h1);
    oh2[i * 2 + 1] = __nv_bfloat162(h2, h3);
    ol2[i * 2]     = __floats2bfloat162_rn(l0, l1);
    ol2[i * 2 + 1] = __floats2bfloat162_rn(l2, l3);
}

// -------------------- W -> W^T hi/lo bf16 --------------------------------------
__global__ void convert_wt_kernel(const float* __restrict__ W0, const float* __restrict__ W1,
                                  const float* __restrict__ W2, const float* __restrict__ W3,
                                  __nv_bfloat16* __restrict__ wth, __nv_bfloat16* __restrict__ wtl) {
    const float* W = (blockIdx.z == 0) ? W0 : (blockIdx.z == 1) ? W1 : (blockIdx.z == 2) ? W2 : W3;
    __shared__ float t[32][33];
    int tx = threadIdx.x, ty = threadIdx.y;
    int k0 = blockIdx.y * 32, n0 = blockIdx.x * 32;
#pragma unroll
    for (int j = 0; j < 4; j++)
        t[ty + 8 * j][tx] = W[(size_t)(k0 + ty + 8 * j) * EE + n0 + tx];
    __syncthreads();
    size_t off = (size_t)blockIdx.z << 20;
#pragma unroll
    for (int j = 0; j < 4; j++) {
        float f = t[tx][ty + 8 * j];
        __nv_bfloat16 h = __float2bfloat16(f);
        size_t o = off + (size_t)(n0 + ty + 8 * j) * EE + k0 + tx;
        wth[o] = h;
        wtl[o] = __float2bfloat16(f - __bfloat162float(h));
    }
}

// -------------------- mma.sync split-bf16 GEMM (KC=32, 2 CTAs/SM) --------------
#define TSZ        8192
#define STAGE_B    (4 * TSZ)
#define GEMM_SMEM  (3 * STAGE_B)
#define NKC        32

__device__ __forceinline__ void load_stage(
    uint32_t sb, const __nv_bfloat16* ah, const __nv_bfloat16* al,
    const __nv_bfloat16* bh, const __nv_bfloat16* bl, int kc, int tid)
{
    const __nv_bfloat16* bases[4] = {ah, al, bh, bl};
#pragma unroll
    for (int t4 = 0; t4 < 4; t4++) {
        const __nv_bfloat16* base = bases[t4] + kc * 32;
        uint32_t dtile = sb + t4 * TSZ;
#pragma unroll
        for (int p = 0; p < 2; p++) {
            int idx = p * 256 + tid;
            int r = idx >> 2, c = idx & 3;
            cp_async16(dtile + r * 64 + ((c ^ ((r >> 1) & 3)) << 4),
                       base + (size_t)r * EE + c * 8);
        }
    }
}

__global__ void __launch_bounds__(256, 2) gemm_mma_kernel(
    const __nv_bfloat16* __restrict__ Ah, const __nv_bfloat16* __restrict__ Al,
    const __nv_bfloat16* __restrict__ Wh, const __nv_bfloat16* __restrict__ Wl,
    const float* __restrict__ b0, const float* __restrict__ b1, const float* __restrict__ b2,
    float* fo, __half* f0, __half* f1, __half* f2,
    int headmajor, int wbase)
{
    extern __shared__ char smem[];
    const uint32_t sbase = smem_u32(smem);
    const int tid = threadIdx.x;
    const int z = blockIdx.z;
    const float* bias = (z == 0) ? b0 : (z == 1) ? b1 : b2;
    __half* hf = (z == 0) ? f0 : (z == 1) ? f1 : f2;
    const size_t woff = ((size_t)(wbase + z)) << 20;

    const int mBase = blockIdx.y * 128;
    const int nBase = blockIdx.x * 128;
    const __nv_bfloat16* ah = Ah + (size_t)mBase * EE;
    const __nv_bfloat16* al = Al + (size_t)mBase * EE;
    const __nv_bfloat16* bh = Wh + woff + (size_t)nBase * EE;
    const __nv_bfloat16* bl = Wl + woff + (size_t)nBase * EE;

    load_stage(sbase + 0 * STAGE_B, ah, al, bh, bl, 0, tid);
    CP_COMMIT();
    load_stage(sbase + 1 * STAGE_B, ah, al, bh, bl, 1, tid);
    CP_COMMIT();

    const int lane = tid & 31;
    const int wm = (tid >> 5) & 1;
    const int wn = tid >> 6;
    const int l15 = lane & 15, l16 = lane >> 4;

    float c[4][4][4];
#pragma unroll
    for (int i = 0; i < 4; i++)
#pragma unroll
        for (int j = 0; j < 4; j++)
#pragma unroll
            for (int q = 0; q < 4; q++) c[i][j][q] = 0.0f;

    for (int kc = 0; kc < NKC; kc++) {
        CP_WAIT1();
        __syncthreads();
        if (kc + 2 < NKC)
            load_stage(sbase + ((kc + 2) % 3) * STAGE_B, ah, al, bh, bl, kc + 2, tid);
        CP_COMMIT();

        const uint32_t sb = sbase + (kc % 3) * STAGE_B;
#pragma unroll
        for (int ko = 0; ko < 2; ko++) {
            uint32_t a[4][4], bh0[4], bh1[4], bl0[4], bl1[4];
            const int ch = ko * 2 + l16;
#pragma unroll
            for (int i = 0; i < 4; i++) {
                int r = wm * 64 + i * 16 + l15;
                ldsm4(a[i], sb + r * 64 + ((ch ^ ((r >> 1) & 3)) << 4));
            }
            {
                int r0 = wn * 32 + l15;
                ldsm4(bh0, sb + 2 * TSZ + r0 * 64 + ((ch ^ ((r0 >> 1) & 3)) << 4));
                int r1 = wn * 32 + 16 + l15;
                ldsm4(bh1, sb + 2 * TSZ + r1 * 64 + ((ch ^ ((r1 >> 1) & 3)) << 4));
                ldsm4(bl0, sb + 3 * TSZ + r0 * 64 + ((ch ^ ((r0 >> 1) & 3)) << 4));
                ldsm4(bl1, sb + 3 * TSZ + r1 * 64 + ((ch ^ ((r1 >> 1) & 3)) << 4));
            }
#pragma unroll
            for (int i = 0; i < 4; i++) {
                mma_bf16(c[i][0], a[i], bh0[0], bh0[2]);
                mma_bf16(c[i][1], a[i], bh0[1], bh0[3]);
                mma_bf16(c[i][2], a[i], bh1[0], bh1[2]);
                mma_bf16(c[i][3], a[i], bh1[1], bh1[3]);
                mma_bf16(c[i][0], a[i], bl0[0], bl0[2]);
                mma_bf16(c[i][1], a[i], bl0[1], bl0[3]);
                mma_bf16(c[i][2], a[i], bl1[0], bl1[2]);
                mma_bf16(c[i][3], a[i], bl1[1], bl1[3]);
            }
#pragma unroll
            for (int i = 0; i < 4; i++) {
                int r = wm * 64 + i * 16 + l15;
                ldsm4(a[i], sb + TSZ + r * 64 + ((ch ^ ((r >> 1) & 3)) << 4));
            }
#pragma unroll
            for (int i = 0; i < 4; i++) {
                mma_bf16(c[i][0], a[i], bh0[0], bh0[2]);
                mma_bf16(c[i][1], a[i], bh0[1], bh0[3]);
                mma_bf16(c[i][2], a[i], bh1[0], bh1[2]);
                mma_bf16(c[i][3], a[i], bh1[1], bh1[3]);
            }
        }
    }

    const int lr = lane >> 2, lc = lane & 3;
#pragma unroll
    for (int i = 0; i < 4; i++) {
#pragma unroll
        for (int half = 0; half < 2; half++) {
            const int R = mBase + wm * 64 + i * 16 + half * 8 + lr;
#pragma unroll
            for (int j = 0; j < 4; j++) {
                const int C0 = nBase + wn * 32 + j * 8 + lc * 2;
                float2 bv = *(const float2*)(bias + C0);
                float vx = c[i][j][half * 2 + 0] + bv.x;
                float vy = c[i][j][half * 2 + 1] + bv.y;
                if (headmajor) {
                    const int nidx = R >> 10, sidx = R & 1023;
                    const int head = C0 >> 6, dd = C0 & 63;
                    size_t off = (((size_t)(nidx * HH + head) * SQ + sidx) << 6) + dd;
                    __half2 hv = __floats2half2_rn(vx, vy);
                    *(__half2*)(hf + off) = hv;
                } else {
                    *(float2*)(fo + (size_t)R * EE + C0) = make_float2(vx, vy);
                }
            }
        }
    }
}

// -------------------- flash attention, fp16 mma --------------------------------
// CTA: 128 q-rows x 1 head; 8 warps x 16 rows; kv tiles of 64.
// smem: Q 16KB + 2 stages x (K 8KB + V 8KB + maskbits 1KB).
#define A_ST0    16384
#define A_STG    17408
#define A_V      8192
#define A_MB     16384
#define ATT_SMEM (A_ST0 + 2 * A_STG)
#define SCL2     0.1803368801111244f   // 0.125 * log2(e)

__device__ __forceinline__ void att_load_stage(
    uint32_t sb, int st, const __half* kf, const __half* vf,
    const unsigned long long* mb, int kt, int tid)
{
    const uint32_t dtile = sb + A_ST0 + st * A_STG;
    const __half* kb = kf + (size_t)kt * 64 * DK;
    const __half* vb = vf + (size_t)kt * 64 * DK;
#pragma unroll
    for (int p = 0; p < 2; p++) {
        int idx = p * 256 + tid;
        int r = idx >> 3, c = idx & 7;
        uint32_t sw = r * 128 + ((c ^ (r & 7)) << 4);
        cp_async16(dtile + sw, kb + r * 64 + c * 8);
        cp_async16(dtile + A_V + sw, vb + r * 64 + c * 8);
    }
    if (tid < 64)
        cp_async16(dtile + A_MB + tid * 16, mb + (size_t)kt * SQ + tid * 2);
}

__global__ void __launch_bounds__(256, 2) attn_mma_kernel(
    const __half* __restrict__ Qf, const __half* __restrict__ Kf,
    const __half* __restrict__ Vf,
    const unsigned long long* __restrict__ maskb,
    __nv_bfloat16* __restrict__ Oh, __nv_bfloat16* __restrict__ Ol)
{
    extern __shared__ char smem[];
    const uint32_t sb = smem_u32(smem);
    const int tid = threadIdx.x;
    const int qt = blockIdx.x, h = blockIdx.y, n = blockIdx.z;

    const size_t hoff = (size_t)(n * HH + h) * SQ * DK;
    const __half* qf = Qf + hoff + (size_t)qt * 128 * DK;
    const __half* kf = Kf + hoff;
    const __half* vf = Vf + hoff;
    const unsigned long long* mb = maskb + (size_t)n * 16 * SQ + qt * 128;

    // Q load (group 0, with stage 0)
#pragma unroll
    for (int p = 0; p < 4; p++) {
        int idx = p * 256 + tid;
        int r = idx >> 3, c = idx & 7;
        cp_async16(sb + r * 128 + ((c ^ (r & 7)) << 4), qf + r * 64 + c * 8);
    }
    att_load_stage(sb, 0, kf, vf, mb, 0, tid);
    CP_COMMIT();

    const int w = tid >> 5, lane = tid & 31;
    const int l15 = lane & 15, l16 = lane >> 4;
    const int lr = lane >> 2, lc = lane & 3;
    const int row0 = w * 16 + lr;
    const int qg0 = qt * 128 + row0;
    const int qg1 = qg0 + 8;

    CP_WAIT0();
    __syncthreads();

    // hoist Q fragments for the whole loop (16 regs)
    uint32_t aq[4][4];
#pragma unroll
    for (int ko = 0; ko < 4; ko++) {
        int r = w * 16 + l15;
        int ch = 2 * ko + l16;
        ldsm4(aq[ko], sb + r * 128 + ((ch ^ (r & 7)) << 4));
    }

    float o[8][4];
#pragma unroll
    for (int i = 0; i < 8; i++)
#pragma unroll
        for (int j = 0; j < 4; j++) o[i][j] = 0.0f;
    float m0 = -1e30f, m1 = -1e30f, l0 = 0.0f, l1 = 0.0f;

    for (int kt = 0; kt < 16; kt++) {
        // prefetch next tile into the other buffer (safe: its last readers
        // finished before the sync that ended the previous iteration)
        if (kt + 1 < 16)
            att_load_stage(sb, (kt + 1) & 1, kf, vf, mb, kt + 1, tid);
        CP_COMMIT();

        const uint32_t stg = sb + A_ST0 + (kt & 1) * A_STG;
        const char* msp = smem + (A_ST0 + (kt & 1) * A_STG + A_MB);

        // ---- S = Q K^T (fp16 single product) ----
        float s[8][4];
#pragma unroll
        for (int i = 0; i < 8; i++)
#pragma unroll
            for (int j = 0; j < 4; j++) s[i][j] = 0.0f;

#pragma unroll
        for (int ko = 0; ko < 4; ko++) {
            const int ch = 2 * ko + l16;
#pragma unroll
            for (int nt2 = 0; nt2 < 4; nt2++) {
                int rk = nt2 * 16 + l15;
                uint32_t kb[4];
                ldsm4(kb, stg + rk * 128 + ((ch ^ (rk & 7)) << 4));
                mma_f16(s[2 * nt2],     aq[ko], kb[0], kb[2]);
                mma_f16(s[2 * nt2 + 1], aq[ko], kb[1], kb[3]);
            }
        }

        // ---- scale (log2 domain) + mask from bit-packed smem ----
        unsigned long long mr0 = *(const unsigned long long*)(msp + row0 * 8);
        unsigned long long mr1 = *(const unsigned long long*)(msp + (row0 + 8) * 8);
#pragma unroll
        for (int nt = 0; nt < 8; nt++) {
            const int c0 = nt * 8 + 2 * lc;
            s[nt][0] = ((mr0 >> c0) & 1)       ? -1e9f : s[nt][0] * SCL2;
            s[nt][1] = ((mr0 >> (c0 + 1)) & 1) ? -1e9f : s[nt][1] * SCL2;
            s[nt][2] = ((mr1 >> c0) & 1)       ? -1e9f : s[nt][2] * SCL2;
            s[nt][3] = ((mr1 >> (c0 + 1)) & 1) ? -1e9f : s[nt][3] * SCL2;
        }

        // ---- online softmax (base-2) ----
        float vx0 = -1e30f, vx1 = -1e30f;
#pragma unroll
        for (int nt = 0; nt < 8; nt++) {
            vx0 = fmaxf(vx0, fmaxf(s[nt][0], s[nt][1]));
            vx1 = fmaxf(vx1, fmaxf(s[nt][2], s[nt][3]));
        }
        vx0 = fmaxf(vx0, __shfl_xor_sync(0xffffffffu, vx0, 1));
        vx0 = fmaxf(vx0, __shfl_xor_sync(0xffffffffu, vx0, 2));
        vx1 = fmaxf(vx1, __shfl_xor_sync(0xffffffffu, vx1, 1));
        vx1 = fmaxf(vx1, __shfl_xor_sync(0xffffffffu, vx1, 2));

        float mn0 = fmaxf(m0, vx0), mn1 = fmaxf(m1, vx1);
        float a0 = exp2f(m0 - mn0), a1 = exp2f(m1 - mn1);
        m0 = mn0; m1 = mn1;
        float sum0 = 0.0f, sum1 = 0.0f;
#pragma unroll
        for (int nt = 0; nt < 8; nt++) {
            s[nt][0] = exp2f(s[nt][0] - mn0);
            s[nt][1] = exp2f(s[nt][1] - mn0);
            s[nt][2] = exp2f(s[nt][2] - mn1);
            s[nt][3] = exp2f(s[nt][3] - mn1);
            sum0 += s[nt][0] + s[nt][1];
            sum1 += s[nt][2] + s[nt][3];
        }
        sum0 += __shfl_xor_sync(0xffffffffu, sum0, 1);
        sum0 += __shfl_xor_sync(0xffffffffu, sum0, 2);
        sum1 += __shfl_xor_sync(0xffffffffu, sum1, 1);
        sum1 += __shfl_xor_sync(0xffffffffu, sum1, 2);
        l0 = l0 * a0 + sum0;
        l1 = l1 * a1 + sum1;
#pragma unroll
        for (int nt = 0; nt < 8; nt++) {
            o[nt][0] *= a0; o[nt][1] *= a0;
            o[nt][2] *= a1; o[nt][3] *= a1;
        }

        // ---- O += P V (fp16 single product) ----
#pragma unroll
        for (int t = 0; t < 4; t++) {
            uint32_t ph[4];
            ph[0] = pack_f16(s[2 * t][0],     s[2 * t][1]);
            ph[1] = pack_f16(s[2 * t][2],     s[2 * t][3]);
            ph[2] = pack_f16(s[2 * t + 1][0], s[2 * t + 1][1]);
            ph[3] = pack_f16(s[2 * t + 1][2], s[2 * t + 1][3]);
#pragma unroll
            for (int dt2 = 0; dt2 < 4; dt2++) {
                int rv = t * 16 + l15;
                int chd = 2 * dt2 + l16;
                uint32_t vb[4];
                ldsm4t(vb, stg + A_V + rv * 128 + ((chd ^ (rv & 7)) << 4));
                mma_f16(o[2 * dt2],     ph, vb[0], vb[1]);
                mma_f16(o[2 * dt2 + 1], ph, vb[2], vb[3]);
            }
        }

        if (kt + 1 < 16) {
            CP_WAIT0();       // drain prefetch for kt+1
            __syncthreads();  // all warps done with current buffer
        }
    }

    // ---- epilogue: normalize, split to bf16 hi/lo, store [n,s,e] ----
    const float inv0 = 1.0f / l0, inv1 = 1.0f / l1;
    const size_t base0 = ((size_t)n * SQ + qg0) * EE + h * DK + 2 * lc;
    const size_t base1 = ((size_t)n * SQ + qg1) * EE + h * DK + 2 * lc;
#pragma unroll
    for (int nt = 0; nt < 8; nt++) {
        float vx = o[nt][0] * inv0, vy = o[nt][1] * inv0;
        __nv_bfloat16 h0 = __float2bfloat16(vx), h1 = __float2bfloat16(vy);
        __nv_bfloat162 hp(h0, h1);
        __nv_bfloat162 lp = __floats2bfloat162_rn(vx - __bfloat162float(h0),
                                                  vy - __bfloat162float(h1));
        *(__nv_bfloat162*)(Oh + base0 + nt * 8) = hp;
        *(__nv_bfloat162*)(Ol + base0 + nt * 8) = lp;

        vx = o[nt][2] * inv1; vy = o[nt][3] * inv1;
        h0 = __float2bfloat16(vx); h1 = __float2bfloat16(vy);
        __nv_bfloat162 hp1(h0, h1);
        __nv_bfloat162 lp1 = __floats2bfloat162_rn(vx - __bfloat162float(h0),
                                                   vy - __bfloat162float(h1));
        *(__nv_bfloat162*)(Oh + base1 + nt * 8) = hp1;
        *(__nv_bfloat162*)(Ol + base1 + nt * 8) = lp1;
    }
}

// -------------------- launch ---------------------------------------------------
extern "C" void kernel_launch(void* const* d_in, const int* in_sizes, int n_in,
                              void* d_out, int out_size)
{
    const float* x    = (const float*)d_in[0];
    const void*  mask = d_in[1];
    const float* Wq   = (const float*)d_in[2];
    const float* bq   = (const float*)d_in[3];
    const float* Wk   = (const float*)d_in[4];
    const float* bk   = (const float*)d_in[5];
    const float* Wv   = (const float*)d_in[6];
    const float* bv   = (const float*)d_in[7];
    const float* Wo   = (const float*)d_in[8];
    const float* bo   = (const float*)d_in[9];
    float* out = (float*)d_out;

    unsigned long long* mb;
    cudaGetSymbolAddress((void**)&mb, g_maskb);
    __nv_bfloat16 *xh, *xl, *wth, *wtl, *aoh, *aol;
    __half *qf, *kf, *vf;
    cudaGetSymbolAddress((void**)&xh,  g_xh);
    cudaGetSymbolAddress((void**)&xl,  g_xl);
    cudaGetSymbolAddress((void**)&wth, g_wth);
    cudaGetSymbolAddress((void**)&wtl, g_wtl);
    cudaGetSymbolAddress((void**)&aoh, g_aoh);
    cudaGetSymbolAddress((void**)&aol, g_aol);
    cudaGetSymbolAddress((void**)&qf,  g_qf);
    cudaGetSymbolAddress((void**)&kf,  g_kf);
    cudaGetSymbolAddress((void**)&vf,  g_vf);

    cudaFuncSetAttribute(gemm_mma_kernel,
                         cudaFuncAttributeMaxDynamicSharedMemorySize, GEMM_SMEM);
    cudaFuncSetAttribute(attn_mma_kernel,
                         cudaFuncAttributeMaxDynamicSharedMemorySize, ATT_SMEM);

    // 1. mask detect + bit-pack
    detect_mask_kernel<<<1, 256>>>((const unsigned int*)mask);
    mask_bits_kernel<<<NB * SQ * 16 * 32 / 256, 256>>>(mask, mb);

    // 2. split x, build W^T hi/lo
    int nelem4 = NB * SQ * EE / 4;
    split_kernel<<<nelem4 / 256, 256>>>(x, xh, xl);
    convert_wt_kernel<<<dim3(32, 32, 4), dim3(32, 8)>>>(Wq, Wk, Wv, Wo, wth, wtl);

    // 3. QKV projections -> fp16 head-major
    gemm_mma_kernel<<<dim3(EE / 128, NB * SQ / 128, 3), 256, GEMM_SMEM>>>(
        xh, xl, wth, wtl, bq, bk, bv, nullptr, qf, kf, vf, 1, 0);

    // 4. flash attention (fp16 tensor cores) -> bf16 hi/lo [n,s,e]
    attn_mma_kernel<<<dim3(SQ / 128, HH, NB), 256, ATT_SMEM>>>(
        qf, kf, vf, mb, aoh, aol);

    // 5. out projection -> f32 out
    gemm_mma_kernel<<<dim3(EE / 128, NB * SQ / 128, 1), 256, GEMM_SMEM>>>(
        aoh, aol, wth, wtl, bo, bo, bo, out,
        nullptr, nullptr, nullptr, 0, 3);
}

// round 10
// speedup vs baseline: 7.2757x; 1.3416x over previous
#include <cuda_runtime.h>
#include <cuda_bf16.h>
#include <cuda_fp16.h>
#include <cstdint>

// Problem dims
#define NB   8
#define SQ   1024
#define EE   1024
#define HH   16
#define DK   64

// -------------------- scratch (static device arrays; no allocation) -----------
__device__ unsigned long long g_maskb[NB * SQ * 16];   // bit-packed, [n][kt][qrow]
__device__ int g_mask_fmt;

__device__ __half g_xf[NB * SQ * EE];            // x fp16
__device__ __half g_wth[4 * EE * EE];            // W^T fp16 hi, [n][k], 4 mats
__device__ __half g_wtl[4 * EE * EE];            // W^T fp16 lo (denormal-range)
__device__ __half g_qf[NB * HH * SQ * DK];       // [n,h,s,d] fp16
__device__ __half g_kf[NB * HH * SQ * DK];
__device__ __half g_vf[NB * HH * SQ * DK];
__device__ __half g_aof[NB * SQ * EE];           // attn-out fp16, [n,s,e]

// -------------------- helpers --------------------------------------------------
__device__ __forceinline__ uint32_t smem_u32(const void* p) {
    uint32_t a;
    asm("{ .reg .u64 t; cvta.to.shared.u64 t, %1; cvt.u32.u64 %0, t; }" : "=r"(a) : "l"(p));
    return a;
}
__device__ __forceinline__ void cp_async16(uint32_t dst, const void* src) {
    asm volatile("cp.async.cg.shared.global [%0], [%1], 16;" :: "r"(dst), "l"(src));
}
#define CP_COMMIT() asm volatile("cp.async.commit_group;" ::: "memory")
#define CP_WAIT1()  asm volatile("cp.async.wait_group 1;" ::: "memory")
#define CP_WAIT0()  asm volatile("cp.async.wait_group 0;" ::: "memory")

__device__ __forceinline__ void ldsm4(uint32_t* r, uint32_t addr) {
    asm volatile("ldmatrix.sync.aligned.m8n8.x4.shared.b16 {%0,%1,%2,%3}, [%4];"
        : "=r"(r[0]), "=r"(r[1]), "=r"(r[2]), "=r"(r[3]) : "r"(addr));
}
__device__ __forceinline__ void ldsm4t(uint32_t* r, uint32_t addr) {
    asm volatile("ldmatrix.sync.aligned.m8n8.x4.trans.shared.b16 {%0,%1,%2,%3}, [%4];"
        : "=r"(r[0]), "=r"(r[1]), "=r"(r[2]), "=r"(r[3]) : "r"(addr));
}
__device__ __forceinline__ void mma_f16(float* c, const uint32_t* a, uint32_t b0, uint32_t b1) {
    asm volatile(
        "mma.sync.aligned.m16n8k16.row.col.f32.f16.f16.f32 "
        "{%0,%1,%2,%3}, {%4,%5,%6,%7}, {%8,%9}, {%0,%1,%2,%3};"
        : "+f"(c[0]), "+f"(c[1]), "+f"(c[2]), "+f"(c[3])
        : "r"(a[0]), "r"(a[1]), "r"(a[2]), "r"(a[3]), "r"(b0), "r"(b1));
}
__device__ __forceinline__ uint32_t pack_f16(float x, float y) {
    __half2 t = __floats2half2_rn(x, y);
    return *(uint32_t*)&t;
}

// -------------------- mask dtype detection + bit packing ----------------------
__global__ void detect_mask_kernel(const unsigned int* __restrict__ m) {
    __shared__ int s01, sf;
    if (threadIdx.x == 0) { s01 = 1; sf = 1; }
    __syncthreads();
    unsigned int v = m[threadIdx.x];
    if (v > 1u) s01 = 0;
    if (v != 0u && v != 0x3F800000u) sf = 0;
    __syncthreads();
    if (threadIdx.x == 0) g_mask_fmt = s01 ? 0 : (sf ? 1 : 2);
}

// one warp -> one u64 word covering 64 mask cols; out layout [n][kt][qrow]
__global__ void mask_bits_kernel(const void* __restrict__ m,
                                 unsigned long long* __restrict__ out) {
    int gw = (blockIdx.x * blockDim.x + threadIdx.x) >> 5;
    int lane = threadIdx.x & 31;
    int n = gw >> 14;
    int rem = gw & 16383;
    int qrow = rem >> 4;
    int kt = rem & 15;
    size_t base = ((size_t)(n * SQ + qrow)) * SQ + kt * 64;
    int fmt = g_mask_fmt;
    unsigned a, b;
    if (fmt == 2) {
        const unsigned char* p = (const unsigned char*)m + base;
        a = (p[lane] != 0); b = (p[lane + 32] != 0);
    } else {
        const unsigned* p = (const unsigned*)m + base;
        unsigned va = p[lane], vb = p[lane + 32];
        if (fmt == 1) { va &= 0x7fffffffu; vb &= 0x7fffffffu; }
        a = (va != 0); b = (vb != 0);
    }
    unsigned lo = __ballot_sync(0xffffffffu, a);
    unsigned hi = __ballot_sync(0xffffffffu, b);
    if (lane == 0)
        out[((size_t)(n * 16 + kt)) * SQ + qrow] =
            ((unsigned long long)hi << 32) | lo;
}

// -------------------- fp32 -> fp16 convert (x) ---------------------------------
__global__ void tohalf_kernel(const float* __restrict__ in, __half* __restrict__ o) {
    int i = blockIdx.x * blockDim.x + threadIdx.x;
    float4 v = ((const float4*)in)[i];
    __half2* o2 = (__half2*)o;
    o2[i * 2]     = __floats2half2_rn(v.x, v.y);
    o2[i * 2 + 1] = __floats2half2_rn(v.z, v.w);
}

// -------------------- W -> W^T fp16 hi + denormal lo ---------------------------
__global__ void convert_wt_kernel(const float* __restrict__ W0, const float* __restrict__ W1,
                                  const float* __restrict__ W2, const float* __restrict__ W3,
                                  __half* __restrict__ wth, __half* __restrict__ wtl) {
    const float* W = (blockIdx.z == 0) ? W0 : (blockIdx.z == 1) ? W1 : (blockIdx.z == 2) ? W2 : W3;
    __shared__ float t[32][33];
    int tx = threadIdx.x, ty = threadIdx.y;
    int k0 = blockIdx.y * 32, n0 = blockIdx.x * 32;
#pragma unroll
    for (int j = 0; j < 4; j++)
        t[ty + 8 * j][tx] = W[(size_t)(k0 + ty + 8 * j) * EE + n0 + tx];
    __syncthreads();
    size_t off = (size_t)blockIdx.z << 20;
#pragma unroll
    for (int j = 0; j < 4; j++) {
        float f = t[tx][ty + 8 * j];
        __half h = __float2half(f);
        size_t o = off + (size_t)(n0 + ty + 8 * j) * EE + k0 + tx;
        wth[o] = h;
        wtl[o] = __float2half(f - __half2float(h));   // denormal-range remainder
    }
}

// -------------------- 2-product fp16 GEMM (KC=32, 2 CTAs/SM) -------------------
// C = A(fp16) @ (Wh + Wl)^T; per k-chunk: A, Wh, Wl tiles of 128x32 fp16 (8KB).
#define TSZ        8192
#define STAGE_B    (3 * TSZ)      // 24KB
#define GEMM_SMEM  (3 * STAGE_B)  // 72KB
#define NKC        32

__device__ __forceinline__ void load_stage(
    uint32_t sb, const __half* af, const __half* bh, const __half* bl,
    int kc, int tid)
{
    const __half* bases[3] = {af, bh, bl};
#pragma unroll
    for (int t3 = 0; t3 < 3; t3++) {
        const __half* base = bases[t3] + kc * 32;
        uint32_t dtile = sb + t3 * TSZ;
#pragma unroll
        for (int p = 0; p < 2; p++) {
            int idx = p * 256 + tid;
            int r = idx >> 2, c = idx & 3;
            cp_async16(dtile + r * 64 + ((c ^ ((r >> 1) & 3)) << 4),
                       base + (size_t)r * EE + c * 8);
        }
    }
}

__global__ void __launch_bounds__(256, 2) gemm_mma_kernel(
    const __half* __restrict__ Af,
    const __half* __restrict__ Wh, const __half* __restrict__ Wl,
    const float* __restrict__ b0, const float* __restrict__ b1, const float* __restrict__ b2,
    float* fo, __half* f0, __half* f1, __half* f2,
    int headmajor, int wbase)
{
    extern __shared__ char smem[];
    const uint32_t sbase = smem_u32(smem);
    const int tid = threadIdx.x;
    const int z = blockIdx.z;
    const float* bias = (z == 0) ? b0 : (z == 1) ? b1 : b2;
    __half* hf = (z == 0) ? f0 : (z == 1) ? f1 : f2;
    const size_t woff = ((size_t)(wbase + z)) << 20;

    const int mBase = blockIdx.y * 128;
    const int nBase = blockIdx.x * 128;
    const __half* af = Af + (size_t)mBase * EE;
    const __half* bh = Wh + woff + (size_t)nBase * EE;
    const __half* bl = Wl + woff + (size_t)nBase * EE;

    load_stage(sbase + 0 * STAGE_B, af, bh, bl, 0, tid);
    CP_COMMIT();
    load_stage(sbase + 1 * STAGE_B, af, bh, bl, 1, tid);
    CP_COMMIT();

    const int lane = tid & 31;
    const int wm = (tid >> 5) & 1;
    const int wn = tid >> 6;
    const int l15 = lane & 15, l16 = lane >> 4;

    float c[4][4][4];
#pragma unroll
    for (int i = 0; i < 4; i++)
#pragma unroll
        for (int j = 0; j < 4; j++)
#pragma unroll
            for (int q = 0; q < 4; q++) c[i][j][q] = 0.0f;

    for (int kc = 0; kc < NKC; kc++) {
        CP_WAIT1();
        __syncthreads();
        if (kc + 2 < NKC)
            load_stage(sbase + ((kc + 2) % 3) * STAGE_B, af, bh, bl, kc + 2, tid);
        CP_COMMIT();

        const uint32_t sb = sbase + (kc % 3) * STAGE_B;
#pragma unroll
        for (int ko = 0; ko < 2; ko++) {
            uint32_t a[4][4], bh0[4], bh1[4], bl0[4], bl1[4];
            const int ch = ko * 2 + l16;
#pragma unroll
            for (int i = 0; i < 4; i++) {
                int r = wm * 64 + i * 16 + l15;
                ldsm4(a[i], sb + r * 64 + ((ch ^ ((r >> 1) & 3)) << 4));
            }
            {
                int r0 = wn * 32 + l15;
                int r1 = wn * 32 + 16 + l15;
                ldsm4(bh0, sb + TSZ + r0 * 64 + ((ch ^ ((r0 >> 1) & 3)) << 4));
                ldsm4(bh1, sb + TSZ + r1 * 64 + ((ch ^ ((r1 >> 1) & 3)) << 4));
                ldsm4(bl0, sb + 2 * TSZ + r0 * 64 + ((ch ^ ((r0 >> 1) & 3)) << 4));
                ldsm4(bl1, sb + 2 * TSZ + r1 * 64 + ((ch ^ ((r1 >> 1) & 3)) << 4));
            }
#pragma unroll
            for (int i = 0; i < 4; i++) {
                mma_f16(c[i][0], a[i], bh0[0], bh0[2]);
                mma_f16(c[i][1], a[i], bh0[1], bh0[3]);
                mma_f16(c[i][2], a[i], bh1[0], bh1[2]);
                mma_f16(c[i][3], a[i], bh1[1], bh1[3]);
                mma_f16(c[i][0], a[i], bl0[0], bl0[2]);
                mma_f16(c[i][1], a[i], bl0[1], bl0[3]);
                mma_f16(c[i][2], a[i], bl1[0], bl1[2]);
                mma_f16(c[i][3], a[i], bl1[1], bl1[3]);
            }
        }
    }

    const int lr = lane >> 2, lc = lane & 3;
#pragma unroll
    for (int i = 0; i < 4; i++) {
#pragma unroll
        for (int half = 0; half < 2; half++) {
            const int R = mBase + wm * 64 + i * 16 + half * 8 + lr;
#pragma unroll
            for (int j = 0; j < 4; j++) {
                const int C0 = nBase + wn * 32 + j * 8 + lc * 2;
                float2 bv = *(const float2*)(bias + C0);
                float vx = c[i][j][half * 2 + 0] + bv.x;
                float vy = c[i][j][half * 2 + 1] + bv.y;
                if (headmajor) {
                    const int nidx = R >> 10, sidx = R & 1023;
                    const int head = C0 >> 6, dd = C0 & 63;
                    size_t off = (((size_t)(nidx * HH + head) * SQ + sidx) << 6) + dd;
                    *(__half2*)(hf + off) = __floats2half2_rn(vx, vy);
                } else {
                    *(float2*)(fo + (size_t)R * EE + C0) = make_float2(vx, vy);
                }
            }
        }
    }
}

// -------------------- flash attention, fp16 mma --------------------------------
// CTA: 128 q-rows x 1 head; 8 warps x 16 rows; kv tiles of 64.
// smem: Q 16KB + 2 stages x (K 8KB + V 8KB + maskbits 1KB).
#define A_ST0    16384
#define A_STG    17408
#define A_V      8192
#define A_MB     16384
#define ATT_SMEM (A_ST0 + 2 * A_STG)
#define SCL2     0.1803368801111244f   // 0.125 * log2(e)

__device__ __forceinline__ void att_load_stage(
    uint32_t sb, int st, const __half* kf, const __half* vf,
    const unsigned long long* mb, int kt, int tid)
{
    const uint32_t dtile = sb + A_ST0 + st * A_STG;
    const __half* kb = kf + (size_t)kt * 64 * DK;
    const __half* vb = vf + (size_t)kt * 64 * DK;
#pragma unroll
    for (int p = 0; p < 2; p++) {
        int idx = p * 256 + tid;
        int r = idx >> 3, c = idx & 7;
        uint32_t sw = r * 128 + ((c ^ (r & 7)) << 4);
        cp_async16(dtile + sw, kb + r * 64 + c * 8);
        cp_async16(dtile + A_V + sw, vb + r * 64 + c * 8);
    }
    if (tid < 64)
        cp_async16(dtile + A_MB + tid * 16, mb + (size_t)kt * SQ + tid * 2);
}

__global__ void __launch_bounds__(256, 2) attn_mma_kernel(
    const __half* __restrict__ Qf, const __half* __restrict__ Kf,
    const __half* __restrict__ Vf,
    const unsigned long long* __restrict__ maskb,
    __half* __restrict__ Of)
{
    extern __shared__ char smem[];
    const uint32_t sb = smem_u32(smem);
    const int tid = threadIdx.x;
    const int qt = blockIdx.x, h = blockIdx.y, n = blockIdx.z;

    const size_t hoff = (size_t)(n * HH + h) * SQ * DK;
    const __half* qf = Qf + hoff + (size_t)qt * 128 * DK;
    const __half* kf = Kf + hoff;
    const __half* vf = Vf + hoff;
    const unsigned long long* mb = maskb + (size_t)n * 16 * SQ + qt * 128;

    // Q load (group 0, with stage 0)
#pragma unroll
    for (int p = 0; p < 4; p++) {
        int idx = p * 256 + tid;
        int r = idx >> 3, c = idx & 7;
        cp_async16(sb + r * 128 + ((c ^ (r & 7)) << 4), qf + r * 64 + c * 8);
    }
    att_load_stage(sb, 0, kf, vf, mb, 0, tid);
    CP_COMMIT();

    const int w = tid >> 5, lane = tid & 31;
    const int l15 = lane & 15, l16 = lane >> 4;
    const int lr = lane >> 2, lc = lane & 3;
    const int row0 = w * 16 + lr;
    const int qg0 = qt * 128 + row0;
    const int qg1 = qg0 + 8;

    CP_WAIT0();
    __syncthreads();

    // hoist Q fragments for the whole loop (16 regs)
    uint32_t aq[4][4];
#pragma unroll
    for (int ko = 0; ko < 4; ko++) {
        int r = w * 16 + l15;
        int ch = 2 * ko + l16;
        ldsm4(aq[ko], sb + r * 128 + ((ch ^ (r & 7)) << 4));
    }

    float o[8][4];
#pragma unroll
    for (int i = 0; i < 8; i++)
#pragma unroll
        for (int j = 0; j < 4; j++) o[i][j] = 0.0f;
    float m0 = -1e30f, m1 = -1e30f, l0 = 0.0f, l1 = 0.0f;

    for (int kt = 0; kt < 16; kt++) {
        // prefetch next tile into the other buffer (safe: its last readers
        // finished before the sync that ended the previous iteration)
        if (kt + 1 < 16)
            att_load_stage(sb, (kt + 1) & 1, kf, vf, mb, kt + 1, tid);
        CP_COMMIT();

        const uint32_t stg = sb + A_ST0 + (kt & 1) * A_STG;
        const char* msp = smem + (A_ST0 + (kt & 1) * A_STG + A_MB);

        // ---- S = Q K^T ----
        float s[8][4];
#pragma unroll
        for (int i = 0; i < 8; i++)
#pragma unroll
            for (int j = 0; j < 4; j++) s[i][j] = 0.0f;

#pragma unroll
        for (int ko = 0; ko < 4; ko++) {
            const int ch = 2 * ko + l16;
#pragma unroll
            for (int nt2 = 0; nt2 < 4; nt2++) {
                int rk = nt2 * 16 + l15;
                uint32_t kb[4];
                ldsm4(kb, stg + rk * 128 + ((ch ^ (rk & 7)) << 4));
                mma_f16(s[2 * nt2],     aq[ko], kb[0], kb[2]);
                mma_f16(s[2 * nt2 + 1], aq[ko], kb[1], kb[3]);
            }
        }

        // ---- scale (log2 domain) + mask from bit-packed smem ----
        unsigned long long mr0 = *(const unsigned long long*)(msp + row0 * 8);
        unsigned long long mr1 = *(const unsigned long long*)(msp + (row0 + 8) * 8);
#pragma unroll
        for (int nt = 0; nt < 8; nt++) {
            const int c0 = nt * 8 + 2 * lc;
            s[nt][0] = ((mr0 >> c0) & 1)       ? -1e9f : s[nt][0] * SCL2;
            s[nt][1] = ((mr0 >> (c0 + 1)) & 1) ? -1e9f : s[nt][1] * SCL2;
            s[nt][2] = ((mr1 >> c0) & 1)       ? -1e9f : s[nt][2] * SCL2;
            s[nt][3] = ((mr1 >> (c0 + 1)) & 1) ? -1e9f : s[nt][3] * SCL2;
        }

        // ---- online softmax (base-2) ----
        float vx0 = -1e30f, vx1 = -1e30f;
#pragma unroll
        for (int nt = 0; nt < 8; nt++) {
            vx0 = fmaxf(vx0, fmaxf(s[nt][0], s[nt][1]));
            vx1 = fmaxf(vx1, fmaxf(s[nt][2], s[nt][3]));
        }
        vx0 = fmaxf(vx0, __shfl_xor_sync(0xffffffffu, vx0, 1));
        vx0 = fmaxf(vx0, __shfl_xor_sync(0xffffffffu, vx0, 2));
        vx1 = fmaxf(vx1, __shfl_xor_sync(0xffffffffu, vx1, 1));
        vx1 = fmaxf(vx1, __shfl_xor_sync(0xffffffffu, vx1, 2));

        float mn0 = fmaxf(m0, vx0), mn1 = fmaxf(m1, vx1);
        float a0 = exp2f(m0 - mn0), a1 = exp2f(m1 - mn1);
        m0 = mn0; m1 = mn1;
        float sum0 = 0.0f, sum1 = 0.0f;
#pragma unroll
        for (int nt = 0; nt < 8; nt++) {
            s[nt][0] = exp2f(s[nt][0] - mn0);
            s[nt][1] = exp2f(s[nt][1] - mn0);
            s[nt][2] = exp2f(s[nt][2] - mn1);
            s[nt][3] = exp2f(s[nt][3] - mn1);
            sum0 += s[nt][0] + s[nt][1];
            sum1 += s[nt][2] + s[nt][3];
        }
        sum0 += __shfl_xor_sync(0xffffffffu, sum0, 1);
        sum0 += __shfl_xor_sync(0xffffffffu, sum0, 2);
        sum1 += __shfl_xor_sync(0xffffffffu, sum1, 1);
        sum1 += __shfl_xor_sync(0xffffffffu, sum1, 2);
        l0 = l0 * a0 + sum0;
        l1 = l1 * a1 + sum1;
#pragma unroll
        for (int nt = 0; nt < 8; nt++) {
            o[nt][0] *= a0; o[nt][1] *= a0;
            o[nt][2] *= a1; o[nt][3] *= a1;
        }

        // ---- O += P V ----
#pragma unroll
        for (int t = 0; t < 4; t++) {
            uint32_t ph[4];
            ph[0] = pack_f16(s[2 * t][0],     s[2 * t][1]);
            ph[1] = pack_f16(s[2 * t][2],     s[2 * t][3]);
            ph[2] = pack_f16(s[2 * t + 1][0], s[2 * t + 1][1]);
            ph[3] = pack_f16(s[2 * t + 1][2], s[2 * t + 1][3]);
#pragma unroll
            for (int dt2 = 0; dt2 < 4; dt2++) {
                int rv = t * 16 + l15;
                int chd = 2 * dt2 + l16;
                uint32_t vb[4];
                ldsm4t(vb, stg + A_V + rv * 128 + ((chd ^ (rv & 7)) << 4));
                mma_f16(o[2 * dt2],     ph, vb[0], vb[1]);
                mma_f16(o[2 * dt2 + 1], ph, vb[2], vb[3]);
            }
        }

        if (kt + 1 < 16) {
            CP_WAIT0();       // drain prefetch for kt+1
            __syncthreads();  // all warps done with current buffer
        }
    }

    // ---- epilogue: normalize, store fp16 [n,s,e] ----
    const float inv0 = 1.0f / l0, inv1 = 1.0f / l1;
    const size_t base0 = ((size_t)n * SQ + qg0) * EE + h * DK + 2 * lc;
    const size_t base1 = ((size_t)n * SQ + qg1) * EE + h * DK + 2 * lc;
#pragma unroll
    for (int nt = 0; nt < 8; nt++) {
        *(__half2*)(Of + base0 + nt * 8) =
            __floats2half2_rn(o[nt][0] * inv0, o[nt][1] * inv0);
        *(__half2*)(Of + base1 + nt * 8) =
            __floats2half2_rn(o[nt][2] * inv1, o[nt][3] * inv1);
    }
}

// -------------------- launch ---------------------------------------------------
extern "C" void kernel_launch(void* const* d_in, const int* in_sizes, int n_in,
                              void* d_out, int out_size)
{
    const float* x    = (const float*)d_in[0];
    const void*  mask = d_in[1];
    const float* Wq   = (const float*)d_in[2];
    const float* bq   = (const float*)d_in[3];
    const float* Wk   = (const float*)d_in[4];
    const float* bk   = (const float*)d_in[5];
    const float* Wv   = (const float*)d_in[6];
    const float* bv   = (const float*)d_in[7];
    const float* Wo   = (const float*)d_in[8];
    const float* bo   = (const float*)d_in[9];
    float* out = (float*)d_out;

    unsigned long long* mb;
    cudaGetSymbolAddress((void**)&mb, g_maskb);
    __half *xf, *wth, *wtl, *qf, *kf, *vf, *aof;
    cudaGetSymbolAddress((void**)&xf,  g_xf);
    cudaGetSymbolAddress((void**)&wth, g_wth);
    cudaGetSymbolAddress((void**)&wtl, g_wtl);
    cudaGetSymbolAddress((void**)&qf,  g_qf);
    cudaGetSymbolAddress((void**)&kf,  g_kf);
    cudaGetSymbolAddress((void**)&vf,  g_vf);
    cudaGetSymbolAddress((void**)&aof, g_aof);

    cudaFuncSetAttribute(gemm_mma_kernel,
                         cudaFuncAttributeMaxDynamicSharedMemorySize, GEMM_SMEM);
    cudaFuncSetAttribute(attn_mma_kernel,
                         cudaFuncAttributeMaxDynamicSharedMemorySize, ATT_SMEM);

    // 1. mask detect + bit-pack
    detect_mask_kernel<<<1, 256>>>((const unsigned int*)mask);
    mask_bits_kernel<<<NB * SQ * 16 * 32 / 256, 256>>>(mask, mb);

    // 2. x -> fp16, W^T -> fp16 hi/lo
    int nelem4 = NB * SQ * EE / 4;
    tohalf_kernel<<<nelem4 / 256, 256>>>(x, xf);
    convert_wt_kernel<<<dim3(32, 32, 4), dim3(32, 8)>>>(Wq, Wk, Wv, Wo, wth, wtl);

    // 3. QKV projections -> fp16 head-major
    gemm_mma_kernel<<<dim3(EE / 128, NB * SQ / 128, 3), 256, GEMM_SMEM>>>(
        xf, wth, wtl, bq, bk, bv, nullptr, qf, kf, vf, 1, 0);

    // 4. flash attention (fp16 tensor cores) -> fp16 [n,s,e]
    attn_mma_kernel<<<dim3(SQ / 128, HH, NB), 256, ATT_SMEM>>>(
        qf, kf, vf, mb, aof);

    // 5. out projection -> f32 out
    gemm_mma_kernel<<<dim3(EE / 128, NB * SQ / 128, 1), 256, GEMM_SMEM>>>(
        aof, wth, wtl, bo, bo, bo, out,
        nullptr, nullptr, nullptr, 0, 3);
}

// round 11
// speedup vs baseline: 10.1581x; 1.3962x over previous
#include <cuda_runtime.h>
#include <cuda_bf16.h>
#include <cuda_fp16.h>
#include <cstdint>

// Problem dims
#define NB   8
#define SQ   1024
#define EE   1024
#define HH   16
#define DK   64

// -------------------- scratch (static device arrays; no allocation) -----------
__device__ unsigned long long g_maskb[NB * SQ * 16];   // bit-packed, [n][kt][qrow]
__device__ int g_mask_fmt;

__device__ __half g_xf[NB * SQ * EE];            // x fp16
__device__ __half g_wth[4 * EE * EE];            // W^T fp16, [n][k], 4 mats
__device__ __half g_qf[NB * HH * SQ * DK];       // [n,h,s,d] fp16
__device__ __half g_kf[NB * HH * SQ * DK];
__device__ __half g_vf[NB * HH * SQ * DK];
__device__ __half g_aof[NB * SQ * EE];           // attn-out fp16, [n,s,e]

// -------------------- helpers --------------------------------------------------
__device__ __forceinline__ uint32_t smem_u32(const void* p) {
    uint32_t a;
    asm("{ .reg .u64 t; cvta.to.shared.u64 t, %1; cvt.u32.u64 %0, t; }" : "=r"(a) : "l"(p));
    return a;
}
__device__ __forceinline__ void cp_async16(uint32_t dst, const void* src) {
    asm volatile("cp.async.cg.shared.global [%0], [%1], 16;" :: "r"(dst), "l"(src));
}
#define CP_COMMIT() asm volatile("cp.async.commit_group;" ::: "memory")
#define CP_WAIT1()  asm volatile("cp.async.wait_group 1;" ::: "memory")
#define CP_WAIT0()  asm volatile("cp.async.wait_group 0;" ::: "memory")

__device__ __forceinline__ void ldsm4(uint32_t* r, uint32_t addr) {
    asm volatile("ldmatrix.sync.aligned.m8n8.x4.shared.b16 {%0,%1,%2,%3}, [%4];"
        : "=r"(r[0]), "=r"(r[1]), "=r"(r[2]), "=r"(r[3]) : "r"(addr));
}
__device__ __forceinline__ void ldsm4t(uint32_t* r, uint32_t addr) {
    asm volatile("ldmatrix.sync.aligned.m8n8.x4.trans.shared.b16 {%0,%1,%2,%3}, [%4];"
        : "=r"(r[0]), "=r"(r[1]), "=r"(r[2]), "=r"(r[3]) : "r"(addr));
}
__device__ __forceinline__ void mma_f16(float* c, const uint32_t* a, uint32_t b0, uint32_t b1) {
    asm volatile(
        "mma.sync.aligned.m16n8k16.row.col.f32.f16.f16.f32 "
        "{%0,%1,%2,%3}, {%4,%5,%6,%7}, {%8,%9}, {%0,%1,%2,%3};"
        : "+f"(c[0]), "+f"(c[1]), "+f"(c[2]), "+f"(c[3])
        : "r"(a[0]), "r"(a[1]), "r"(a[2]), "r"(a[3]), "r"(b0), "r"(b1));
}
__device__ __forceinline__ uint32_t pack_f16(float x, float y) {
    __half2 t = __floats2half2_rn(x, y);
    return *(uint32_t*)&t;
}

// -------------------- mask dtype detection + bit packing ----------------------
__global__ void detect_mask_kernel(const unsigned int* __restrict__ m) {
    __shared__ int s01, sf;
    if (threadIdx.x == 0) { s01 = 1; sf = 1; }
    __syncthreads();
    unsigned int v = m[threadIdx.x];
    if (v > 1u) s01 = 0;
    if (v != 0u && v != 0x3F800000u) sf = 0;
    __syncthreads();
    if (threadIdx.x == 0) g_mask_fmt = s01 ? 0 : (sf ? 1 : 2);
}

// one warp -> one u64 word covering 64 mask cols; out layout [n][kt][qrow]
__global__ void mask_bits_kernel(const void* __restrict__ m,
                                 unsigned long long* __restrict__ out) {
    int gw = (blockIdx.x * blockDim.x + threadIdx.x) >> 5;
    int lane = threadIdx.x & 31;
    int n = gw >> 14;
    int rem = gw & 16383;
    int qrow = rem >> 4;
    int kt = rem & 15;
    size_t base = ((size_t)(n * SQ + qrow)) * SQ + kt * 64;
    int fmt = g_mask_fmt;
    unsigned a, b;
    if (fmt == 2) {
        const unsigned char* p = (const unsigned char*)m + base;
        a = (p[lane] != 0); b = (p[lane + 32] != 0);
    } else {
        const unsigned* p = (const unsigned*)m + base;
        unsigned va = p[lane], vb = p[lane + 32];
        if (fmt == 1) { va &= 0x7fffffffu; vb &= 0x7fffffffu; }
        a = (va != 0); b = (vb != 0);
    }
    unsigned lo = __ballot_sync(0xffffffffu, a);
    unsigned hi = __ballot_sync(0xffffffffu, b);
    if (lane == 0)
        out[((size_t)(n * 16 + kt)) * SQ + qrow] =
            ((unsigned long long)hi << 32) | lo;
}

// -------------------- fp32 -> fp16 convert (x) ---------------------------------
__global__ void tohalf_kernel(const float* __restrict__ in, __half* __restrict__ o) {
    int i = blockIdx.x * blockDim.x + threadIdx.x;
    float4 v = ((const float4*)in)[i];
    __half2* o2 = (__half2*)o;
    o2[i * 2]     = __floats2half2_rn(v.x, v.y);
    o2[i * 2 + 1] = __floats2half2_rn(v.z, v.w);
}

// -------------------- W -> W^T fp16 ---------------------------------------------
__global__ void convert_wt_kernel(const float* __restrict__ W0, const float* __restrict__ W1,
                                  const float* __restrict__ W2, const float* __restrict__ W3,
                                  __half* __restrict__ wth) {
    const float* W = (blockIdx.z == 0) ? W0 : (blockIdx.z == 1) ? W1 : (blockIdx.z == 2) ? W2 : W3;
    __shared__ float t[32][33];
    int tx = threadIdx.x, ty = threadIdx.y;
    int k0 = blockIdx.y * 32, n0 = blockIdx.x * 32;
#pragma unroll
    for (int j = 0; j < 4; j++)
        t[ty + 8 * j][tx] = W[(size_t)(k0 + ty + 8 * j) * EE + n0 + tx];
    __syncthreads();
    size_t off = (size_t)blockIdx.z << 20;
#pragma unroll
    for (int j = 0; j < 4; j++)
        wth[off + (size_t)(n0 + ty + 8 * j) * EE + k0 + tx] =
            __float2half(t[tx][ty + 8 * j]);
}

// -------------------- single-product fp16 GEMM (KC=32, 2 CTAs/SM) --------------
// C = A(fp16) @ Wh^T; per k-chunk: A, Wh tiles of 128x32 fp16 (8KB each).
#define TSZ        8192
#define STAGE_B    (2 * TSZ)      // 16KB
#define GEMM_SMEM  (3 * STAGE_B)  // 48KB
#define NKC        32

__device__ __forceinline__ void load_stage(
    uint32_t sb, const __half* af, const __half* bh, int kc, int tid)
{
    const __half* bases[2] = {af, bh};
#pragma unroll
    for (int t2 = 0; t2 < 2; t2++) {
        const __half* base = bases[t2] + kc * 32;
        uint32_t dtile = sb + t2 * TSZ;
#pragma unroll
        for (int p = 0; p < 2; p++) {
            int idx = p * 256 + tid;
            int r = idx >> 2, c = idx & 3;
            cp_async16(dtile + r * 64 + ((c ^ ((r >> 1) & 3)) << 4),
                       base + (size_t)r * EE + c * 8);
        }
    }
}

__global__ void __launch_bounds__(256, 2) gemm_mma_kernel(
    const __half* __restrict__ Af, const __half* __restrict__ Wh,
    const float* __restrict__ b0, const float* __restrict__ b1, const float* __restrict__ b2,
    float* fo, __half* f0, __half* f1, __half* f2,
    int headmajor, int wbase)
{
    extern __shared__ char smem[];
    const uint32_t sbase = smem_u32(smem);
    const int tid = threadIdx.x;
    const int z = blockIdx.z;
    const float* bias = (z == 0) ? b0 : (z == 1) ? b1 : b2;
    __half* hf = (z == 0) ? f0 : (z == 1) ? f1 : f2;
    const size_t woff = ((size_t)(wbase + z)) << 20;

    const int mBase = blockIdx.y * 128;
    const int nBase = blockIdx.x * 128;
    const __half* af = Af + (size_t)mBase * EE;
    const __half* bh = Wh + woff + (size_t)nBase * EE;

    load_stage(sbase + 0 * STAGE_B, af, bh, 0, tid);
    CP_COMMIT();
    load_stage(sbase + 1 * STAGE_B, af, bh, 1, tid);
    CP_COMMIT();

    const int lane = tid & 31;
    const int wm = (tid >> 5) & 1;
    const int wn = tid >> 6;
    const int l15 = lane & 15, l16 = lane >> 4;

    float c[4][4][4];
#pragma unroll
    for (int i = 0; i < 4; i++)
#pragma unroll
        for (int j = 0; j < 4; j++)
#pragma unroll
            for (int q = 0; q < 4; q++) c[i][j][q] = 0.0f;

    for (int kc = 0; kc < NKC; kc++) {
        CP_WAIT1();
        __syncthreads();
        if (kc + 2 < NKC)
            load_stage(sbase + ((kc + 2) % 3) * STAGE_B, af, bh, kc + 2, tid);
        CP_COMMIT();

        const uint32_t sb = sbase + (kc % 3) * STAGE_B;
#pragma unroll
        for (int ko = 0; ko < 2; ko++) {
            uint32_t a[4][4], bh0[4], bh1[4];
            const int ch = ko * 2 + l16;
#pragma unroll
            for (int i = 0; i < 4; i++) {
                int r = wm * 64 + i * 16 + l15;
                ldsm4(a[i], sb + r * 64 + ((ch ^ ((r >> 1) & 3)) << 4));
            }
            {
                int r0 = wn * 32 + l15;
                int r1 = wn * 32 + 16 + l15;
                ldsm4(bh0, sb + TSZ + r0 * 64 + ((ch ^ ((r0 >> 1) & 3)) << 4));
                ldsm4(bh1, sb + TSZ + r1 * 64 + ((ch ^ ((r1 >> 1) & 3)) << 4));
            }
#pragma unroll
            for (int i = 0; i < 4; i++) {
                mma_f16(c[i][0], a[i], bh0[0], bh0[2]);
                mma_f16(c[i][1], a[i], bh0[1], bh0[3]);
                mma_f16(c[i][2], a[i], bh1[0], bh1[2]);
                mma_f16(c[i][3], a[i], bh1[1], bh1[3]);
            }
        }
    }

    const int lr = lane >> 2, lc = lane & 3;
#pragma unroll
    for (int i = 0; i < 4; i++) {
#pragma unroll
        for (int half = 0; half < 2; half++) {
            const int R = mBase + wm * 64 + i * 16 + half * 8 + lr;
#pragma unroll
            for (int j = 0; j < 4; j++) {
                const int C0 = nBase + wn * 32 + j * 8 + lc * 2;
                float2 bv = *(const float2*)(bias + C0);
                float vx = c[i][j][half * 2 + 0] + bv.x;
                float vy = c[i][j][half * 2 + 1] + bv.y;
                if (headmajor) {
                    const int nidx = R >> 10, sidx = R & 1023;
                    const int head = C0 >> 6, dd = C0 & 63;
                    size_t off = (((size_t)(nidx * HH + head) * SQ + sidx) << 6) + dd;
                    *(__half2*)(hf + off) = __floats2half2_rn(vx, vy);
                } else {
                    *(float2*)(fo + (size_t)R * EE + C0) = make_float2(vx, vy);
                }
            }
        }
    }
}

// -------------------- flash attention, fp16 mma --------------------------------
// CTA: 128 q-rows x 1 head; 8 warps x 16 rows; kv tiles of 64.
// smem: Q 16KB + 2 stages x (K 8KB + V 8KB + maskbits 1KB).
#define A_ST0    16384
#define A_STG    17408
#define A_V      8192
#define A_MB     16384
#define ATT_SMEM (A_ST0 + 2 * A_STG)
#define SCL2     0.1803368801111244f   // 0.125 * log2(e)

__device__ __forceinline__ void att_load_stage(
    uint32_t sb, int st, const __half* kf, const __half* vf,
    const unsigned long long* mb, int kt, int tid)
{
    const uint32_t dtile = sb + A_ST0 + st * A_STG;
    const __half* kb = kf + (size_t)kt * 64 * DK;
    const __half* vb = vf + (size_t)kt * 64 * DK;
#pragma unroll
    for (int p = 0; p < 2; p++) {
        int idx = p * 256 + tid;
        int r = idx >> 3, c = idx & 7;
        uint32_t sw = r * 128 + ((c ^ (r & 7)) << 4);
        cp_async16(dtile + sw, kb + r * 64 + c * 8);
        cp_async16(dtile + A_V + sw, vb + r * 64 + c * 8);
    }
    if (tid < 64)
        cp_async16(dtile + A_MB + tid * 16, mb + (size_t)kt * SQ + tid * 2);
}

__global__ void __launch_bounds__(256, 2) attn_mma_kernel(
    const __half* __restrict__ Qf, const __half* __restrict__ Kf,
    const __half* __restrict__ Vf,
    const unsigned long long* __restrict__ maskb,
    __half* __restrict__ Of)
{
    extern __shared__ char smem[];
    const uint32_t sb = smem_u32(smem);
    const int tid = threadIdx.x;
    const int qt = blockIdx.x, h = blockIdx.y, n = blockIdx.z;

    const size_t hoff = (size_t)(n * HH + h) * SQ * DK;
    const __half* qf = Qf + hoff + (size_t)qt * 128 * DK;
    const __half* kf = Kf + hoff;
    const __half* vf = Vf + hoff;
    const unsigned long long* mb = maskb + (size_t)n * 16 * SQ + qt * 128;

    // Q load (group 0, with stage 0)
#pragma unroll
    for (int p = 0; p < 4; p++) {
        int idx = p * 256 + tid;
        int r = idx >> 3, c = idx & 7;
        cp_async16(sb + r * 128 + ((c ^ (r & 7)) << 4), qf + r * 64 + c * 8);
    }
    att_load_stage(sb, 0, kf, vf, mb, 0, tid);
    CP_COMMIT();

    const int w = tid >> 5, lane = tid & 31;
    const int l15 = lane & 15, l16 = lane >> 4;
    const int lr = lane >> 2, lc = lane & 3;
    const int row0 = w * 16 + lr;
    const int qg0 = qt * 128 + row0;
    const int qg1 = qg0 + 8;

    CP_WAIT0();
    __syncthreads();

    // hoist Q fragments for the whole loop (16 regs)
    uint32_t aq[4][4];
#pragma unroll
    for (int ko = 0; ko < 4; ko++) {
        int r = w * 16 + l15;
        int ch = 2 * ko + l16;
        ldsm4(aq[ko], sb + r * 128 + ((ch ^ (r & 7)) << 4));
    }

    float o[8][4];
#pragma unroll
    for (int i = 0; i < 8; i++)
#pragma unroll
        for (int j = 0; j < 4; j++) o[i][j] = 0.0f;
    float m0 = -1e30f, m1 = -1e30f, l0 = 0.0f, l1 = 0.0f;

    for (int kt = 0; kt < 16; kt++) {
        // prefetch next tile into the other buffer (safe: its last readers
        // finished before the sync that ended the previous iteration)
        if (kt + 1 < 16)
            att_load_stage(sb, (kt + 1) & 1, kf, vf, mb, kt + 1, tid);
        CP_COMMIT();

        const uint32_t stg = sb + A_ST0 + (kt & 1) * A_STG;
        const char* msp = smem + (A_ST0 + (kt & 1) * A_STG + A_MB);

        // ---- S = Q K^T ----
        float s[8][4];
#pragma unroll
        for (int i = 0; i < 8; i++)
#pragma unroll
            for (int j = 0; j < 4; j++) s[i][j] = 0.0f;

#pragma unroll
        for (int ko = 0; ko < 4; ko++) {
            const int ch = 2 * ko + l16;
#pragma unroll
            for (int nt2 = 0; nt2 < 4; nt2++) {
                int rk = nt2 * 16 + l15;
                uint32_t kb[4];
                ldsm4(kb, stg + rk * 128 + ((ch ^ (rk & 7)) << 4));
                mma_f16(s[2 * nt2],     aq[ko], kb[0], kb[2]);
                mma_f16(s[2 * nt2 + 1], aq[ko], kb[1], kb[3]);
            }
        }

        // ---- scale (log2 domain) + mask from bit-packed smem ----
        unsigned long long mr0 = *(const unsigned long long*)(msp + row0 * 8);
        unsigned long long mr1 = *(const unsigned long long*)(msp + (row0 + 8) * 8);
#pragma unroll
        for (int nt = 0; nt < 8; nt++) {
            const int c0 = nt * 8 + 2 * lc;
            s[nt][0] = ((mr0 >> c0) & 1)       ? -1e9f : s[nt][0] * SCL2;
            s[nt][1] = ((mr0 >> (c0 + 1)) & 1) ? -1e9f : s[nt][1] * SCL2;
            s[nt][2] = ((mr1 >> c0) & 1)       ? -1e9f : s[nt][2] * SCL2;
            s[nt][3] = ((mr1 >> (c0 + 1)) & 1) ? -1e9f : s[nt][3] * SCL2;
        }

        // ---- online softmax (base-2) ----
        float vx0 = -1e30f, vx1 = -1e30f;
#pragma unroll
        for (int nt = 0; nt < 8; nt++) {
            vx0 = fmaxf(vx0, fmaxf(s[nt][0], s[nt][1]));
            vx1 = fmaxf(vx1, fmaxf(s[nt][2], s[nt][3]));
        }
        vx0 = fmaxf(vx0, __shfl_xor_sync(0xffffffffu, vx0, 1));
        vx0 = fmaxf(vx0, __shfl_xor_sync(0xffffffffu, vx0, 2));
        vx1 = fmaxf(vx1, __shfl_xor_sync(0xffffffffu, vx1, 1));
        vx1 = fmaxf(vx1, __shfl_xor_sync(0xffffffffu, vx1, 2));

        float mn0 = fmaxf(m0, vx0), mn1 = fmaxf(m1, vx1);
        float a0 = exp2f(m0 - mn0), a1 = exp2f(m1 - mn1);
        m0 = mn0; m1 = mn1;
        float sum0 = 0.0f, sum1 = 0.0f;
#pragma unroll
        for (int nt = 0; nt < 8; nt++) {
            s[nt][0] = exp2f(s[nt][0] - mn0);
            s[nt][1] = exp2f(s[nt][1] - mn0);
            s[nt][2] = exp2f(s[nt][2] - mn1);
            s[nt][3] = exp2f(s[nt][3] - mn1);
            sum0 += s[nt][0] + s[nt][1];
            sum1 += s[nt][2] + s[nt][3];
        }
        sum0 += __shfl_xor_sync(0xffffffffu, sum0, 1);
        sum0 += __shfl_xor_sync(0xffffffffu, sum0, 2);
        sum1 += __shfl_xor_sync(0xffffffffu, sum1, 1);
        sum1 += __shfl_xor_sync(0xffffffffu, sum1, 2);
        l0 = l0 * a0 + sum0;
        l1 = l1 * a1 + sum1;
#pragma unroll
        for (int nt = 0; nt < 8; nt++) {
            o[nt][0] *= a0; o[nt][1] *= a0;
            o[nt][2] *= a1; o[nt][3] *= a1;
        }

        // ---- O += P V ----
#pragma unroll
        for (int t = 0; t < 4; t++) {
            uint32_t ph[4];
            ph[0] = pack_f16(s[2 * t][0],     s[2 * t][1]);
            ph[1] = pack_f16(s[2 * t][2],     s[2 * t][3]);
            ph[2] = pack_f16(s[2 * t + 1][0], s[2 * t + 1][1]);
            ph[3] = pack_f16(s[2 * t + 1][2], s[2 * t + 1][3]);
#pragma unroll
            for (int dt2 = 0; dt2 < 4; dt2++) {
                int rv = t * 16 + l15;
                int chd = 2 * dt2 + l16;
                uint32_t vb[4];
                ldsm4t(vb, stg + A_V + rv * 128 + ((chd ^ (rv & 7)) << 4));
                mma_f16(o[2 * dt2],     ph, vb[0], vb[1]);
                mma_f16(o[2 * dt2 + 1], ph, vb[2], vb[3]);
            }
        }

        if (kt + 1 < 16) {
            CP_WAIT0();       // drain prefetch for kt+1
            __syncthreads();  // all warps done with current buffer
        }
    }

    // ---- epilogue: normalize, store fp16 [n,s,e] ----
    const float inv0 = 1.0f / l0, inv1 = 1.0f / l1;
    const size_t base0 = ((size_t)n * SQ + qg0) * EE + h * DK + 2 * lc;
    const size_t base1 = ((size_t)n * SQ + qg1) * EE + h * DK + 2 * lc;
#pragma unroll
    for (int nt = 0; nt < 8; nt++) {
        *(__half2*)(Of + base0 + nt * 8) =
            __floats2half2_rn(o[nt][0] * inv0, o[nt][1] * inv0);
        *(__half2*)(Of + base1 + nt * 8) =
            __floats2half2_rn(o[nt][2] * inv1, o[nt][3] * inv1);
    }
}

// -------------------- launch ---------------------------------------------------
extern "C" void kernel_launch(void* const* d_in, const int* in_sizes, int n_in,
                              void* d_out, int out_size)
{
    const float* x    = (const float*)d_in[0];
    const void*  mask = d_in[1];
    const float* Wq   = (const float*)d_in[2];
    const float* bq   = (const float*)d_in[3];
    const float* Wk   = (const float*)d_in[4];
    const float* bk   = (const float*)d_in[5];
    const float* Wv   = (const float*)d_in[6];
    const float* bv   = (const float*)d_in[7];
    const float* Wo   = (const float*)d_in[8];
    const float* bo   = (const float*)d_in[9];
    float* out = (float*)d_out;

    unsigned long long* mb;
    cudaGetSymbolAddress((void**)&mb, g_maskb);
    __half *xf, *wth, *qf, *kf, *vf, *aof;
    cudaGetSymbolAddress((void**)&xf,  g_xf);
    cudaGetSymbolAddress((void**)&wth, g_wth);
    cudaGetSymbolAddress((void**)&qf,  g_qf);
    cudaGetSymbolAddress((void**)&kf,  g_kf);
    cudaGetSymbolAddress((void**)&vf,  g_vf);
    cudaGetSymbolAddress((void**)&aof, g_aof);

    cudaFuncSetAttribute(gemm_mma_kernel,
                         cudaFuncAttributeMaxDynamicSharedMemorySize, GEMM_SMEM);
    cudaFuncSetAttribute(attn_mma_kernel,
                         cudaFuncAttributeMaxDynamicSharedMemorySize, ATT_SMEM);

    // 1. mask detect + bit-pack
    detect_mask_kernel<<<1, 256>>>((const unsigned int*)mask);
    mask_bits_kernel<<<NB * SQ * 16 * 32 / 256, 256>>>(mask, mb);

    // 2. x -> fp16, W^T -> fp16
    int nelem4 = NB * SQ * EE / 4;
    tohalf_kernel<<<nelem4 / 256, 256>>>(x, xf);
    convert_wt_kernel<<<dim3(32, 32, 4), dim3(32, 8)>>>(Wq, Wk, Wv, Wo, wth);

    // 3. QKV projections -> fp16 head-major
    gemm_mma_kernel<<<dim3(EE / 128, NB * SQ / 128, 3), 256, GEMM_SMEM>>>(
        xf, wth, bq, bk, bv, nullptr, qf, kf, vf, 1, 0);

    // 4. flash attention (fp16 tensor cores) -> fp16 [n,s,e]
    attn_mma_kernel<<<dim3(SQ / 128, HH, NB), 256, ATT_SMEM>>>(
        qf, kf, vf, mb, aof);

    // 5. out projection -> f32 out
    gemm_mma_kernel<<<dim3(EE / 128, NB * SQ / 128, 1), 256, GEMM_SMEM>>>(
        aof, wth, bo, bo, bo, out,
        nullptr, nullptr, nullptr, 0, 3);
}